// round 5
// baseline (speedup 1.0000x reference)
#include <cuda_runtime.h>
#include <cstdint>
#include <math.h>

#define B_  2
#define T_  2048
#define C_  1024
#define H_  16
#define D_  64
#define BT_ 4096

// ---------------- scratch (allocation-free contract: __device__ globals) ----
__device__ float g_q[BT_ * C_];
__device__ float g_k[BT_ * C_];
__device__ float g_v[BT_ * C_];
__device__ float g_att[BT_ * C_];

// ---------------- helpers ---------------------------------------------------
__device__ __forceinline__ uint32_t smem_u32(const void* p) {
    uint32_t a;
    asm("{ .reg .u64 t; cvta.to.shared.u64 t, %1; cvt.u32.u64 %0, t; }"
        : "=r"(a) : "l"(p));
    return a;
}

__device__ __forceinline__ uint32_t f2tf(float x) {
    uint32_t u;
    asm("cvt.rna.tf32.f32 %0, %1;" : "=r"(u) : "f"(x));
    return u;
}

__device__ __forceinline__ void mma_tf32(float c[4], const uint32_t a[4],
                                         const uint32_t b[2]) {
    asm volatile(
        "mma.sync.aligned.m16n8k8.row.col.f32.tf32.tf32.f32 "
        "{%0,%1,%2,%3}, {%4,%5,%6,%7}, {%8,%9}, {%0,%1,%2,%3};\n"
        : "+f"(c[0]), "+f"(c[1]), "+f"(c[2]), "+f"(c[3])
        : "r"(a[0]), "r"(a[1]), "r"(a[2]), "r"(a[3]),
          "r"(b[0]), "r"(b[1]));
}

__device__ __forceinline__ void cpa16(uint32_t saddr, const void* g) {
    asm volatile("cp.async.cg.shared.global [%0], [%1], 16;"
                 :: "r"(saddr), "l"(g) : "memory");
}
#define CP_COMMIT() asm volatile("cp.async.commit_group;" ::: "memory")
#define CP_WAIT1()  asm volatile("cp.async.wait_group 1;" ::: "memory")

// rope on an (even, odd) in-head pair. Matches reference rotate_half-interleaved.
__device__ __forceinline__ void rope2(float& e, float& o, float t,
                                      float f0, float f1, float scale) {
    float s0, c0, s1, c1;
    sincosf(t * f0, &s0, &c0);
    sincosf(t * f1, &s1, &c1);
    float en = (e * c0 - o * s0) * scale;
    float on = (o * c1 + e * s1) * scale;
    e = en; o = on;
}

#define ROPE_LG 0.41524103786091404f   // log2(10000)*2/64

// ---------------- tf32 GEMM: C[M,N] = A[M,K] @ W[N,K]^T + bias --------------
// block 128x128, BK=16, 256 threads = 8 warps (warp tile 32m x 64n).
// k-paired smem layout (pos p(k)=2*(k&3)+(k>>2) within each 8-k group) so
// fragments load as LDS.64. Stride 24 words: reads {24g+2tg} conflict-free.
#define GSTR 24

__device__ __forceinline__ void gemm_tf32_body(
    const float* __restrict__ A, const float* __restrict__ W,
    const float* __restrict__ bias, float* __restrict__ Cm,
    int bx, int by, int mode)
{
    __shared__ uint32_t Asu[2][128 * GSTR];
    __shared__ uint32_t Bsu[2][128 * GSTR];

    const int K = C_, N = C_;
    const int tid  = threadIdx.x;
    const int warp = tid >> 5;
    const int lane = tid & 31;
    const int g    = lane >> 2;
    const int tg   = lane & 3;
    const int m0   = (warp & 3) * 32;
    const int n0   = (warp >> 2) * 64;
    const int bm   = by * 128;
    const int bn   = bx * 128;

    const float* Ap = A + (size_t)bm * K;
    const float* Wp = W + (size_t)bn * K;

    float acc[2][8][4];
#pragma unroll
    for (int mt = 0; mt < 2; ++mt)
#pragma unroll
        for (int nt = 0; nt < 8; ++nt)
#pragma unroll
            for (int i = 0; i < 4; ++i) acc[mt][nt][i] = 0.f;

    float4 ra[2], rb[2];
#pragma unroll
    for (int i = 0; i < 2; ++i) {
        int f = tid + (i << 8);
        int r = f >> 2, c = (f & 3) << 2;
        ra[i] = *(const float4*)(Ap + (size_t)r * K + c);
        rb[i] = *(const float4*)(Wp + (size_t)r * K + c);
    }

    const int NKB = K / 16;   // 64
    for (int kb = 0; kb < NKB; ++kb) {
        uint32_t* As = Asu[kb & 1];
        uint32_t* Bs = Bsu[kb & 1];
#pragma unroll
        for (int i = 0; i < 2; ++i) {
            int f  = tid + (i << 8);
            int r  = f >> 2;
            int c4 = (f & 3) << 2;                  // k base (0,4,8,12)
            int base = r * GSTR + ((c4 >> 3) << 3) + ((c4 >> 2) & 1);
            As[base + 0] = f2tf(ra[i].x);
            As[base + 2] = f2tf(ra[i].y);
            As[base + 4] = f2tf(ra[i].z);
            As[base + 6] = f2tf(ra[i].w);
            Bs[base + 0] = f2tf(rb[i].x);
            Bs[base + 2] = f2tf(rb[i].y);
            Bs[base + 4] = f2tf(rb[i].z);
            Bs[base + 6] = f2tf(rb[i].w);
        }
        __syncthreads();

        if (kb + 1 < NKB) {
            int kofs = (kb + 1) * 16;
#pragma unroll
            for (int i = 0; i < 2; ++i) {
                int f = tid + (i << 8);
                int r = f >> 2, c = (f & 3) << 2;
                ra[i] = *(const float4*)(Ap + (size_t)r * K + kofs + c);
                rb[i] = *(const float4*)(Wp + (size_t)r * K + kofs + c);
            }
        }

#pragma unroll
        for (int ks = 0; ks < 2; ++ks) {
            const int k0p = ks * 8;                 // position-octet base
            uint32_t a[2][4], b[8][2];
#pragma unroll
            for (int mt = 0; mt < 2; ++mt) {
                int row = m0 + mt * 16 + g;
                uint2 lo = *(const uint2*)&As[row * GSTR + k0p + 2 * tg];
                uint2 hi = *(const uint2*)&As[(row + 8) * GSTR + k0p + 2 * tg];
                a[mt][0] = lo.x; a[mt][2] = lo.y;
                a[mt][1] = hi.x; a[mt][3] = hi.y;
            }
#pragma unroll
            for (int nt = 0; nt < 8; ++nt) {
                int rn = n0 + nt * 8 + g;
                uint2 bb = *(const uint2*)&Bs[rn * GSTR + k0p + 2 * tg];
                b[nt][0] = bb.x; b[nt][1] = bb.y;
            }
#pragma unroll
            for (int mt = 0; mt < 2; ++mt)
#pragma unroll
                for (int nt = 0; nt < 8; ++nt)
                    mma_tf32(acc[mt][nt], a[mt], b[nt]);
        }
    }

    // ---- epilogue: bias (+ optional rope/scale/round), write --------------
    const bool do_rope = (mode == 1 || mode == 2);
    const float rscale = (mode == 1) ? 0.125f : 1.f;
#pragma unroll
    for (int nt = 0; nt < 8; ++nt) {
        int col = bn + n0 + nt * 8 + (tg << 1);
        float2 bv = *(const float2*)(bias + col);
        float f0 = 0.f, f1 = 0.f;
        if (do_rope) {
            int d0 = col & (D_ - 1);
            f0 = exp2f(-ROPE_LG * (float)(d0 & 31));
            f1 = exp2f(-ROPE_LG * (float)((d0 + 1) & 31));
        }
#pragma unroll
        for (int mt = 0; mt < 2; ++mt) {
            int row = bm + m0 + mt * 16 + g;
            float e0 = acc[mt][nt][0] + bv.x, o0 = acc[mt][nt][1] + bv.y;
            float e1 = acc[mt][nt][2] + bv.x, o1 = acc[mt][nt][3] + bv.y;
            if (do_rope) {
                rope2(e0, o0, (float)(row & (T_ - 1)), f0, f1, rscale);
                rope2(e1, o1, (float)((row + 8) & (T_ - 1)), f0, f1, rscale);
            }
            float2 w0, w1;
            if (mode != 0) {
                w0.x = __uint_as_float(f2tf(e0));
                w0.y = __uint_as_float(f2tf(o0));
                w1.x = __uint_as_float(f2tf(e1));
                w1.y = __uint_as_float(f2tf(o1));
            } else {
                w0.x = e0; w0.y = o0;
                w1.x = e1; w1.y = o1;
            }
            *(float2*)(Cm + (size_t)row * N + col)       = w0;
            *(float2*)(Cm + (size_t)(row + 8) * N + col) = w1;
        }
    }
}

__global__ __launch_bounds__(256, 2) void qkv_kernel(
    const float* __restrict__ x,
    const float* __restrict__ wq, const float* __restrict__ bq,
    const float* __restrict__ wk, const float* __restrict__ bk,
    const float* __restrict__ wv, const float* __restrict__ bv)
{
    const float* W; const float* bb; float* out; int mode;
    int z = blockIdx.z;
    if (z == 0)      { W = wq; bb = bq; out = g_q; mode = 1; }
    else if (z == 1) { W = wk; bb = bk; out = g_k; mode = 2; }
    else             { W = wv; bb = bv; out = g_v; mode = 3; }
    gemm_tf32_body(x, W, bb, out, blockIdx.x, blockIdx.y, mode);
}

__global__ __launch_bounds__(256, 2) void out_kernel(
    const float* __restrict__ wo, const float* __restrict__ bo,
    float* __restrict__ out)
{
    gemm_tf32_body(g_att, wo, bo, out, blockIdx.x, blockIdx.y, 0);
}

// ---------------- flash attention (tf32 warp-mma, Br=256, Bc=64) -----------
// 256 threads = 8 warps; each warp owns 32 q-rows (mt=2) so every K/V
// fragment feeds 2 MMAs. K/V double-buffered via cp.async.
// Layouts: Q,P k-paired stride 72; K linear stride 68; V linear stride 72.
#define FQ_STR 72
#define FK_STR 68
#define FV_STR 72
#define FP_STR 72
#define FL_QS   0
#define FL_KS   (256 * FQ_STR)                     // 18432
#define FL_VS   (FL_KS + 2 * 64 * FK_STR)          // 27136
#define FL_PS   (FL_VS + 2 * 64 * FV_STR)          // 36352
#define FL_WORDS (FL_PS + 256 * FP_STR)            // 54784
#define FSMEM_BYTES (FL_WORDS * 4)                 // 219136

__global__ __launch_bounds__(256) void flash_kernel()
{
    extern __shared__ uint32_t sm[];
    uint32_t* Qs = sm + FL_QS;
    uint32_t* Ps = sm + FL_PS;

    const int bh = blockIdx.y;
    const int b  = bh >> 4;
    const int h  = bh & 15;
    const int t0 = blockIdx.x << 8;                // 256 q-rows per CTA
    const int tid  = threadIdx.x;
    const int warp = tid >> 5;
    const int lane = tid & 31;
    const int g    = lane >> 2;
    const int tg   = lane & 3;
    const int m0   = warp << 5;                    // warp's 32-row base

    const uint32_t smem_base = smem_u32(sm);
    const float* Kg0 = g_k + (size_t)(b * T_) * C_ + h * D_;
    const float* Vg0 = g_v + (size_t)(b * T_) * C_ + h * D_;

    // ---- issue cp.async stage for kt into buffer kt&1 ----
    auto issue_stage = [&](int kt) {
        const int buf = kt & 1;
        const float* Kg = Kg0 + (size_t)(kt << 6) * C_;
        const float* Vg = Vg0 + (size_t)(kt << 6) * C_;
#pragma unroll
        for (int i = 0; i < 4; ++i) {
            int f = tid + (i << 8);
            int r = f >> 4, c = (f & 15) << 2;
            cpa16(smem_base + ((FL_KS + buf * 64 * FK_STR + r * FK_STR + c) << 2),
                  Kg + (size_t)r * C_ + c);
            cpa16(smem_base + ((FL_VS + buf * 64 * FV_STR + r * FV_STR + c) << 2),
                  Vg + (size_t)r * C_ + c);
        }
    };

    issue_stage(0);
    CP_COMMIT();

    // ---- load Q block (256 rows), k-paired layout; bits already tf32 ----
    const float* Qg = g_q + (size_t)(b * T_ + t0) * C_ + h * D_;
#pragma unroll
    for (int it = 0; it < 16; ++it) {
        int f  = tid + (it << 8);
        int r  = f >> 4;
        int c4 = (f & 15) << 2;
        float4 v = *(const float4*)(Qg + (size_t)r * C_ + c4);
        int base = r * FQ_STR + ((c4 >> 3) << 3) + ((c4 >> 2) & 1);
        Qs[base + 0] = __float_as_uint(v.x);
        Qs[base + 2] = __float_as_uint(v.y);
        Qs[base + 4] = __float_as_uint(v.z);
        Qs[base + 6] = __float_as_uint(v.w);
    }

    float oacc[2][8][4];
    float m_r[4], l_r[4];
#pragma unroll
    for (int mt = 0; mt < 2; ++mt)
#pragma unroll
        for (int nt = 0; nt < 8; ++nt)
#pragma unroll
            for (int i = 0; i < 4; ++i) oacc[mt][nt][i] = 0.f;
#pragma unroll
    for (int i = 0; i < 4; ++i) { m_r[i] = -1e30f; l_r[i] = 0.f; }

    // P store positions for the C-fragment column pair (2tg, 2tg+1)
    const int kp0 = 2 * tg;
    const int pp0 = ((kp0 & 3) << 1) | (kp0 >> 2);
    const int pp1 = (((kp0 + 1) & 3) << 1) | ((kp0 + 1) >> 2);

    const int NKT = T_ / 64;   // 32
    for (int kt = 0; kt < NKT; ++kt) {
        if (kt + 1 < NKT) issue_stage(kt + 1);
        CP_COMMIT();
        CP_WAIT1();
        __syncthreads();

        const uint32_t* Kb = sm + FL_KS + (kt & 1) * 64 * FK_STR;
        const uint32_t* Vb = sm + FL_VS + (kt & 1) * 64 * FV_STR;

        // ---- S = Q @ K^T ----
        float sacc[2][8][4];
#pragma unroll
        for (int mt = 0; mt < 2; ++mt)
#pragma unroll
            for (int nt = 0; nt < 8; ++nt)
#pragma unroll
                for (int i = 0; i < 4; ++i) sacc[mt][nt][i] = 0.f;

#pragma unroll
        for (int ks = 0; ks < 8; ++ks) {
            const int k0  = ks << 3;               // linear k base (K tile)
            uint32_t a[2][4];
#pragma unroll
            for (int mt = 0; mt < 2; ++mt) {
                int row = m0 + mt * 16 + g;
                uint2 lo = *(const uint2*)&Qs[row * FQ_STR + k0 + 2 * tg];
                uint2 hi = *(const uint2*)&Qs[(row + 8) * FQ_STR + k0 + 2 * tg];
                a[mt][0] = lo.x; a[mt][2] = lo.y;
                a[mt][1] = hi.x; a[mt][3] = hi.y;
            }
#pragma unroll
            for (int nt = 0; nt < 8; ++nt) {
                uint32_t bfr[2];
                int rn = (nt << 3) + g;
                bfr[0] = Kb[rn * FK_STR + k0 + tg];
                bfr[1] = Kb[rn * FK_STR + k0 + tg + 4];
                mma_tf32(sacc[0][nt], a[0], bfr);
                mma_tf32(sacc[1][nt], a[1], bfr);
            }
        }

        // ---- online softmax (4 row-groups: mt*16 + {g, g+8}) ----
#pragma unroll
        for (int mt = 0; mt < 2; ++mt) {
            float mx0 = -1e30f, mx1 = -1e30f;
#pragma unroll
            for (int nt = 0; nt < 8; ++nt) {
                mx0 = fmaxf(mx0, fmaxf(sacc[mt][nt][0], sacc[mt][nt][1]));
                mx1 = fmaxf(mx1, fmaxf(sacc[mt][nt][2], sacc[mt][nt][3]));
            }
            mx0 = fmaxf(mx0, __shfl_xor_sync(0xffffffffu, mx0, 1));
            mx0 = fmaxf(mx0, __shfl_xor_sync(0xffffffffu, mx0, 2));
            mx1 = fmaxf(mx1, __shfl_xor_sync(0xffffffffu, mx1, 1));
            mx1 = fmaxf(mx1, __shfl_xor_sync(0xffffffffu, mx1, 2));

            float mn0 = fmaxf(m_r[mt * 2 + 0], mx0);
            float mn1 = fmaxf(m_r[mt * 2 + 1], mx1);
            float corr0 = __expf(m_r[mt * 2 + 0] - mn0);
            float corr1 = __expf(m_r[mt * 2 + 1] - mn1);

            float rs0 = 0.f, rs1 = 0.f;
#pragma unroll
            for (int nt = 0; nt < 8; ++nt) {
                float p0 = __expf(sacc[mt][nt][0] - mn0);
                float p1 = __expf(sacc[mt][nt][1] - mn0);
                float p2 = __expf(sacc[mt][nt][2] - mn1);
                float p3 = __expf(sacc[mt][nt][3] - mn1);
                rs0 += p0 + p1;
                rs1 += p2 + p3;
                sacc[mt][nt][0] = p0; sacc[mt][nt][1] = p1;
                sacc[mt][nt][2] = p2; sacc[mt][nt][3] = p3;
            }
            rs0 += __shfl_xor_sync(0xffffffffu, rs0, 1);
            rs0 += __shfl_xor_sync(0xffffffffu, rs0, 2);
            rs1 += __shfl_xor_sync(0xffffffffu, rs1, 1);
            rs1 += __shfl_xor_sync(0xffffffffu, rs1, 2);

            l_r[mt * 2 + 0] = l_r[mt * 2 + 0] * corr0 + rs0;
            l_r[mt * 2 + 1] = l_r[mt * 2 + 1] * corr1 + rs1;
            m_r[mt * 2 + 0] = mn0;
            m_r[mt * 2 + 1] = mn1;

#pragma unroll
            for (int nt = 0; nt < 8; ++nt) {
                oacc[mt][nt][0] *= corr0; oacc[mt][nt][1] *= corr0;
                oacc[mt][nt][2] *= corr1; oacc[mt][nt][3] *= corr1;
            }

            // write P (tf32) into warp-private k-paired smem rows
            int row = m0 + mt * 16 + g;
#pragma unroll
            for (int nt = 0; nt < 8; ++nt) {
                int basel = row * FP_STR + (nt << 3);
                int baseh = (row + 8) * FP_STR + (nt << 3);
                Ps[basel + pp0] = f2tf(sacc[mt][nt][0]);
                Ps[basel + pp1] = f2tf(sacc[mt][nt][1]);
                Ps[baseh + pp0] = f2tf(sacc[mt][nt][2]);
                Ps[baseh + pp1] = f2tf(sacc[mt][nt][3]);
            }
        }
        __syncwarp();

        // ---- O += P @ V ----
#pragma unroll
        for (int ks = 0; ks < 8; ++ks) {
            const int k0 = ks << 3;
            uint32_t a[2][4];
#pragma unroll
            for (int mt = 0; mt < 2; ++mt) {
                int row = m0 + mt * 16 + g;
                uint2 lo = *(const uint2*)&Ps[row * FP_STR + k0 + 2 * tg];
                uint2 hi = *(const uint2*)&Ps[(row + 8) * FP_STR + k0 + 2 * tg];
                a[mt][0] = lo.x; a[mt][2] = lo.y;
                a[mt][1] = hi.x; a[mt][3] = hi.y;
            }
#pragma unroll
            for (int nt = 0; nt < 8; ++nt) {
                uint32_t bfr[2];
                bfr[0] = Vb[(k0 + tg) * FV_STR + (nt << 3) + g];
                bfr[1] = Vb[(k0 + tg + 4) * FV_STR + (nt << 3) + g];
                mma_tf32(oacc[0][nt], a[0], bfr);
                mma_tf32(oacc[1][nt], a[1], bfr);
            }
        }
        __syncthreads();   // all warps done with this K/V buffer
    }

    // ---- epilogue: normalize, write concat-head layout ----
    float* Og = g_att + (size_t)(b * T_ + t0) * C_ + h * D_;
#pragma unroll
    for (int mt = 0; mt < 2; ++mt) {
        float inv0 = 1.f / l_r[mt * 2 + 0];
        float inv1 = 1.f / l_r[mt * 2 + 1];
        int row = m0 + mt * 16 + g;
#pragma unroll
        for (int nt = 0; nt < 8; ++nt) {
            int col = (nt << 3) + (tg << 1);
            float2 o0 = make_float2(oacc[mt][nt][0] * inv0,
                                    oacc[mt][nt][1] * inv0);
            float2 o1 = make_float2(oacc[mt][nt][2] * inv1,
                                    oacc[mt][nt][3] * inv1);
            *(float2*)(Og + (size_t)row * C_ + col)       = o0;
            *(float2*)(Og + (size_t)(row + 8) * C_ + col) = o1;
        }
    }
}

// ---------------- launch ---------------------------------------------------
extern "C" void kernel_launch(void* const* d_in, const int* in_sizes, int n_in,
                              void* d_out, int out_size)
{
    const float* x  = (const float*)d_in[0];
    const float* wq = (const float*)d_in[1];
    const float* bq = (const float*)d_in[2];
    const float* wk = (const float*)d_in[3];
    const float* bk = (const float*)d_in[4];
    const float* wv = (const float*)d_in[5];
    const float* bv = (const float*)d_in[6];
    const float* wo = (const float*)d_in[7];
    const float* bo = (const float*)d_in[8];
    float* out = (float*)d_out;

    cudaFuncSetAttribute(flash_kernel,
                         cudaFuncAttributeMaxDynamicSharedMemorySize, FSMEM_BYTES);

    qkv_kernel<<<dim3(C_ / 128, BT_ / 128, 3), 256>>>(x, wq, bq, wk, bk, wv, bv);
    flash_kernel<<<dim3(T_ / 256, B_ * H_), 256, FSMEM_BYTES>>>();
    out_kernel<<<dim3(C_ / 128, BT_ / 128), 256>>>(wo, bo, out);
}

// round 6
// speedup vs baseline: 1.2696x; 1.2696x over previous
#include <cuda_runtime.h>
#include <cstdint>
#include <math.h>

#define B_  2
#define T_  2048
#define C_  1024
#define H_  16
#define D_  64
#define BT_ 4096

// ---------------- scratch (allocation-free contract: __device__ globals) ----
__device__ float g_q[BT_ * C_];
__device__ float g_k[BT_ * C_];
__device__ float g_v[BT_ * C_];
__device__ float g_att[BT_ * C_];          // tf32 bits after flash
__device__ float g_xt[BT_ * C_];           // x pre-rounded to tf32 bits
__device__ float g_wt[4 * C_ * C_];        // wq,wk,wv,wo pre-rounded

// ---------------- helpers ---------------------------------------------------
__device__ __forceinline__ uint32_t smem_u32(const void* p) {
    uint32_t a;
    asm("{ .reg .u64 t; cvta.to.shared.u64 t, %1; cvt.u32.u64 %0, t; }"
        : "=r"(a) : "l"(p));
    return a;
}

__device__ __forceinline__ uint32_t f2tf(float x) {
    uint32_t u;
    asm("cvt.rna.tf32.f32 %0, %1;" : "=r"(u) : "f"(x));
    return u;
}

__device__ __forceinline__ void mma_tf32(float c[4], const uint32_t a[4],
                                         const uint32_t b[2]) {
    asm volatile(
        "mma.sync.aligned.m16n8k8.row.col.f32.tf32.tf32.f32 "
        "{%0,%1,%2,%3}, {%4,%5,%6,%7}, {%8,%9}, {%0,%1,%2,%3};\n"
        : "+f"(c[0]), "+f"(c[1]), "+f"(c[2]), "+f"(c[3])
        : "r"(a[0]), "r"(a[1]), "r"(a[2]), "r"(a[3]),
          "r"(b[0]), "r"(b[1]));
}

__device__ __forceinline__ void cpa16(uint32_t saddr, const void* g) {
    asm volatile("cp.async.cg.shared.global [%0], [%1], 16;"
                 :: "r"(saddr), "l"(g) : "memory");
}
#define CP_COMMIT() asm volatile("cp.async.commit_group;" ::: "memory")
#define CP_WAIT1()  asm volatile("cp.async.wait_group 1;" ::: "memory")
#define CP_WAIT0()  asm volatile("cp.async.wait_group 0;" ::: "memory")

__device__ __forceinline__ void rope2(float& e, float& o, float t,
                                      float f0, float f1, float scale) {
    float s0, c0, s1, c1;
    sincosf(t * f0, &s0, &c0);
    sincosf(t * f1, &s1, &c1);
    float en = (e * c0 - o * s0) * scale;
    float on = (o * c1 + e * s1) * scale;
    e = en; o = on;
}

#define ROPE_LG 0.41524103786091404f   // log2(10000)*2/64

// ---------------- tf32 pre-convert kernels ---------------------------------
__global__ __launch_bounds__(256) void convx_kernel(const float* __restrict__ s)
{
    int i = blockIdx.x * 256 + threadIdx.x;        // over 1M float4
    float4 v = ((const float4*)s)[i];
    uint4 u = make_uint4(f2tf(v.x), f2tf(v.y), f2tf(v.z), f2tf(v.w));
    ((uint4*)g_xt)[i] = u;
}

__global__ __launch_bounds__(256) void convw_kernel(
    const float* __restrict__ wq, const float* __restrict__ wk,
    const float* __restrict__ wv, const float* __restrict__ wo)
{
    const float* src;
    int z = blockIdx.y;
    if (z == 0)      src = wq;
    else if (z == 1) src = wk;
    else if (z == 2) src = wv;
    else             src = wo;
    int i = blockIdx.x * 256 + threadIdx.x;        // over 256K float4
    float4 v = ((const float4*)src)[i];
    uint4 u = make_uint4(f2tf(v.x), f2tf(v.y), f2tf(v.z), f2tf(v.w));
    ((uint4*)(g_wt + (size_t)z * C_ * C_))[i] = u;
}

// ---------------- tf32 GEMM: C[M,N] = A[M,K] @ W[N,K]^T + bias --------------
// A and W hold tf32 bits already. block 128x128, BK=32, 256 threads = 8 warps
// (warp tile 32m x 64n). cp.async double buffer, stride 36 (conflict-free).
#define GSTR 36
#define G_STAGE_W (2 * 128 * GSTR)        // A+B words per stage = 9216
#define G_SMEM_BYTES (2 * G_STAGE_W * 4)  // 73728

__device__ __forceinline__ void gemm_tf32_body(
    const float* __restrict__ A, const float* __restrict__ W,
    const float* __restrict__ bias, float* __restrict__ Cm,
    int bx, int by, int mode)
{
    extern __shared__ uint32_t gsm[];

    const int K = C_, N = C_;
    const int tid  = threadIdx.x;
    const int warp = tid >> 5;
    const int lane = tid & 31;
    const int g    = lane >> 2;
    const int tg   = lane & 3;
    const int m0   = (warp & 3) * 32;
    const int n0   = (warp >> 2) * 64;
    const int bm   = by * 128;
    const int bn   = bx * 128;

    const uint32_t smem_base = smem_u32(gsm);
    const float* Ap = A + (size_t)bm * K;
    const float* Wp = W + (size_t)bn * K;

    float acc[2][8][4];
#pragma unroll
    for (int mt = 0; mt < 2; ++mt)
#pragma unroll
        for (int nt = 0; nt < 8; ++nt)
#pragma unroll
            for (int i = 0; i < 4; ++i) acc[mt][nt][i] = 0.f;

    auto issue = [&](int kb) {
        const int buf = kb & 1;
        uint32_t sa = smem_base + (buf * G_STAGE_W) * 4;
        uint32_t sb = sa + 128 * GSTR * 4;
        const float* Ak = Ap + kb * 32;
        const float* Wk = Wp + kb * 32;
#pragma unroll
        for (int i = 0; i < 4; ++i) {
            int id = tid + (i << 8);
            int r  = id >> 3;
            int cw = (id & 7) << 2;
            cpa16(sa + (r * GSTR + cw) * 4, Ak + (size_t)r * K + cw);
            cpa16(sb + (r * GSTR + cw) * 4, Wk + (size_t)r * K + cw);
        }
    };

    issue(0);
    CP_COMMIT();

    const int NKB = K / 32;   // 32
    for (int kb = 0; kb < NKB; ++kb) {
        if (kb + 1 < NKB) {
            issue(kb + 1);
            CP_COMMIT();
            CP_WAIT1();
        } else {
            CP_WAIT0();
        }
        __syncthreads();

        const uint32_t* As = gsm + (kb & 1) * G_STAGE_W;
        const uint32_t* Bs = As + 128 * GSTR;

#pragma unroll
        for (int ks = 0; ks < 4; ++ks) {
            const int k0 = ks * 8;
            uint32_t a[2][4], b[8][2];
#pragma unroll
            for (int mt = 0; mt < 2; ++mt) {
                int row = m0 + mt * 16 + g;
                a[mt][0] = As[row * GSTR + k0 + tg];
                a[mt][1] = As[(row + 8) * GSTR + k0 + tg];
                a[mt][2] = As[row * GSTR + k0 + tg + 4];
                a[mt][3] = As[(row + 8) * GSTR + k0 + tg + 4];
            }
#pragma unroll
            for (int nt = 0; nt < 8; ++nt) {
                int rn = n0 + nt * 8 + g;
                b[nt][0] = Bs[rn * GSTR + k0 + tg];
                b[nt][1] = Bs[rn * GSTR + k0 + tg + 4];
            }
#pragma unroll
            for (int mt = 0; mt < 2; ++mt)
#pragma unroll
                for (int nt = 0; nt < 8; ++nt)
                    mma_tf32(acc[mt][nt], a[mt], b[nt]);
        }
        __syncthreads();
    }

    // ---- epilogue: bias (+ optional rope/scale/round), write --------------
    const bool do_rope = (mode == 1 || mode == 2);
    const float rscale = (mode == 1) ? 0.125f : 1.f;
#pragma unroll
    for (int nt = 0; nt < 8; ++nt) {
        int col = bn + n0 + nt * 8 + (tg << 1);
        float2 bv = *(const float2*)(bias + col);
        float f0 = 0.f, f1 = 0.f;
        if (do_rope) {
            int d0 = col & (D_ - 1);
            f0 = exp2f(-ROPE_LG * (float)(d0 & 31));
            f1 = exp2f(-ROPE_LG * (float)((d0 + 1) & 31));
        }
#pragma unroll
        for (int mt = 0; mt < 2; ++mt) {
            int row = bm + m0 + mt * 16 + g;
            float e0 = acc[mt][nt][0] + bv.x, o0 = acc[mt][nt][1] + bv.y;
            float e1 = acc[mt][nt][2] + bv.x, o1 = acc[mt][nt][3] + bv.y;
            if (do_rope) {
                rope2(e0, o0, (float)(row & (T_ - 1)), f0, f1, rscale);
                rope2(e1, o1, (float)((row + 8) & (T_ - 1)), f0, f1, rscale);
            }
            float2 w0, w1;
            if (mode != 0) {
                w0.x = __uint_as_float(f2tf(e0));
                w0.y = __uint_as_float(f2tf(o0));
                w1.x = __uint_as_float(f2tf(e1));
                w1.y = __uint_as_float(f2tf(o1));
            } else {
                w0.x = e0; w0.y = o0;
                w1.x = e1; w1.y = o1;
            }
            *(float2*)(Cm + (size_t)row * N + col)       = w0;
            *(float2*)(Cm + (size_t)(row + 8) * N + col) = w1;
        }
    }
}

__global__ __launch_bounds__(256, 2) void qkv_kernel(
    const float* __restrict__ bq, const float* __restrict__ bk,
    const float* __restrict__ bv)
{
    const float* bb; float* out; int mode;
    int z = blockIdx.z;
    if (z == 0)      { bb = bq; out = g_q; mode = 1; }
    else if (z == 1) { bb = bk; out = g_k; mode = 2; }
    else             { bb = bv; out = g_v; mode = 3; }
    gemm_tf32_body(g_xt, g_wt + (size_t)z * C_ * C_, bb, out,
                   blockIdx.x, blockIdx.y, mode);
}

__global__ __launch_bounds__(256, 2) void out_kernel(
    const float* __restrict__ bo, float* __restrict__ out)
{
    gemm_tf32_body(g_att, g_wt + (size_t)3 * C_ * C_, bo, out,
                   blockIdx.x, blockIdx.y, 0);
}

// ---------------- flash attention (tf32 warp-mma, Br=128, Bc=64) -----------
// 256 threads = 8 warps, each warp owns 16 q-rows. K/V double-buffered via
// cp.async. PV A-fragments built from S C-fragments with shuffles (no P smem).
// smem = Q(128x68) + 2 stages of K(64x68)+V(64x72) = 26624 words = 106496 B
// -> 2 CTAs/SM.
#define FQ_STR 68
#define FK_STR 68
#define FV_STR 72
#define FL_QS   0
#define FL_KV   (128 * FQ_STR)                       // 8704
#define FL_STAGE_W (64 * FK_STR + 64 * FV_STR)       // 8960
#define FL_WORDS (FL_KV + 2 * FL_STAGE_W)            // 26624
#define FSMEM_BYTES (FL_WORDS * 4)                   // 106496

__global__ __launch_bounds__(256, 2) void flash_kernel()
{
    extern __shared__ uint32_t sm[];
    uint32_t* Qs = sm + FL_QS;

    const int bh = blockIdx.y;
    const int b  = bh >> 4;
    const int h  = bh & 15;
    const int t0 = blockIdx.x << 7;                  // 128 q-rows per CTA
    const int tid  = threadIdx.x;
    const int warp = tid >> 5;
    const int lane = tid & 31;
    const int g    = lane >> 2;
    const int tg   = lane & 3;
    const int m0   = warp << 4;

    const uint32_t smem_base = smem_u32(sm);
    const float* Kg0 = g_k + (size_t)(b * T_) * C_ + h * D_;
    const float* Vg0 = g_v + (size_t)(b * T_) * C_ + h * D_;

    auto issue_kv = [&](int kt) {
        const int buf = kt & 1;
        const uint32_t ks_base = smem_base + (FL_KV + buf * FL_STAGE_W) * 4;
        const uint32_t vs_base = ks_base + 64 * FK_STR * 4;
        const float* Kg = Kg0 + (size_t)(kt << 6) * C_;
        const float* Vg = Vg0 + (size_t)(kt << 6) * C_;
#pragma unroll
        for (int i = 0; i < 4; ++i) {
            int f = tid + (i << 8);
            int r = f >> 4, c = (f & 15) << 2;
            cpa16(ks_base + (r * FK_STR + c) * 4, Kg + (size_t)r * C_ + c);
            cpa16(vs_base + (r * FV_STR + c) * 4, Vg + (size_t)r * C_ + c);
        }
    };

    issue_kv(0);
    CP_COMMIT();

    // ---- load Q block (128 rows); bits already tf32 ----
    const float* Qg = g_q + (size_t)(b * T_ + t0) * C_ + h * D_;
#pragma unroll
    for (int it = 0; it < 8; ++it) {
        int f = tid + (it << 8);
        int r = f >> 4, c = (f & 15) << 2;
        float4 v = *(const float4*)(Qg + (size_t)r * C_ + c);
        float* p = (float*)&Qs[r * FQ_STR + c];
        *(float2*)p       = make_float2(v.x, v.y);
        *(float2*)(p + 2) = make_float2(v.z, v.w);
    }

    float oacc[8][4];
    float m_r[2], l_r[2];
#pragma unroll
    for (int nt = 0; nt < 8; ++nt)
#pragma unroll
        for (int i = 0; i < 4; ++i) oacc[nt][i] = 0.f;
    m_r[0] = m_r[1] = -1e30f;
    l_r[0] = l_r[1] = 0.f;

    const int srcA = (lane & 28) | (tg >> 1);
    const int srcB = srcA | 2;
    const bool odd = (tg & 1);

    const int NKT = T_ / 64;   // 32
    for (int kt = 0; kt < NKT; ++kt) {
        if (kt + 1 < NKT) {
            issue_kv(kt + 1);
            CP_COMMIT();
            CP_WAIT1();
        } else {
            CP_WAIT0();
        }
        __syncthreads();

        const uint32_t* Kb = sm + FL_KV + (kt & 1) * FL_STAGE_W;
        const uint32_t* Vb = Kb + 64 * FK_STR;

        // ---- S = Q @ K^T ----
        float sacc[8][4];
#pragma unroll
        for (int nt = 0; nt < 8; ++nt)
#pragma unroll
            for (int i = 0; i < 4; ++i) sacc[nt][i] = 0.f;

#pragma unroll
        for (int ks = 0; ks < 8; ++ks) {
            const int k0 = ks << 3;
            uint32_t a[4];
            int row = m0 + g;
            a[0] = Qs[row * FQ_STR + k0 + tg];
            a[1] = Qs[(row + 8) * FQ_STR + k0 + tg];
            a[2] = Qs[row * FQ_STR + k0 + tg + 4];
            a[3] = Qs[(row + 8) * FQ_STR + k0 + tg + 4];
#pragma unroll
            for (int nt = 0; nt < 8; ++nt) {
                uint32_t bfr[2];
                int rn = (nt << 3) + g;
                bfr[0] = Kb[rn * FK_STR + k0 + tg];
                bfr[1] = Kb[rn * FK_STR + k0 + tg + 4];
                mma_tf32(sacc[nt], a, bfr);
            }
        }

        // ---- online softmax (rows g, g+8) ----
        float mx0 = -1e30f, mx1 = -1e30f;
#pragma unroll
        for (int nt = 0; nt < 8; ++nt) {
            mx0 = fmaxf(mx0, fmaxf(sacc[nt][0], sacc[nt][1]));
            mx1 = fmaxf(mx1, fmaxf(sacc[nt][2], sacc[nt][3]));
        }
        mx0 = fmaxf(mx0, __shfl_xor_sync(0xffffffffu, mx0, 1));
        mx0 = fmaxf(mx0, __shfl_xor_sync(0xffffffffu, mx0, 2));
        mx1 = fmaxf(mx1, __shfl_xor_sync(0xffffffffu, mx1, 1));
        mx1 = fmaxf(mx1, __shfl_xor_sync(0xffffffffu, mx1, 2));

        float mn0 = fmaxf(m_r[0], mx0);
        float mn1 = fmaxf(m_r[1], mx1);
        float corr0 = __expf(m_r[0] - mn0);
        float corr1 = __expf(m_r[1] - mn1);

        float rs0 = 0.f, rs1 = 0.f;
#pragma unroll
        for (int nt = 0; nt < 8; ++nt) {
            float p0 = __expf(sacc[nt][0] - mn0);
            float p1 = __expf(sacc[nt][1] - mn0);
            float p2 = __expf(sacc[nt][2] - mn1);
            float p3 = __expf(sacc[nt][3] - mn1);
            rs0 += p0 + p1;
            rs1 += p2 + p3;
            sacc[nt][0] = p0; sacc[nt][1] = p1;
            sacc[nt][2] = p2; sacc[nt][3] = p3;
        }
        rs0 += __shfl_xor_sync(0xffffffffu, rs0, 1);
        rs0 += __shfl_xor_sync(0xffffffffu, rs0, 2);
        rs1 += __shfl_xor_sync(0xffffffffu, rs1, 1);
        rs1 += __shfl_xor_sync(0xffffffffu, rs1, 2);

        l_r[0] = l_r[0] * corr0 + rs0;
        l_r[1] = l_r[1] * corr1 + rs1;
        m_r[0] = mn0;
        m_r[1] = mn1;

#pragma unroll
        for (int nt = 0; nt < 8; ++nt) {
            oacc[nt][0] *= corr0; oacc[nt][1] *= corr0;
            oacc[nt][2] *= corr1; oacc[nt][3] *= corr1;
        }

        // ---- O += P @ V, A-fragments via shuffles (no smem round-trip) ----
#pragma unroll
        for (int ks = 0; ks < 8; ++ks) {
            uint32_t u0 = f2tf(sacc[ks][0]);
            uint32_t u1 = f2tf(sacc[ks][1]);
            uint32_t u2 = f2tf(sacc[ks][2]);
            uint32_t u3 = f2tf(sacc[ks][3]);
            uint32_t a[4], x0, x1;
            x0 = __shfl_sync(0xffffffffu, u0, srcA);
            x1 = __shfl_sync(0xffffffffu, u1, srcA);
            a[0] = odd ? x1 : x0;
            x0 = __shfl_sync(0xffffffffu, u2, srcA);
            x1 = __shfl_sync(0xffffffffu, u3, srcA);
            a[1] = odd ? x1 : x0;
            x0 = __shfl_sync(0xffffffffu, u0, srcB);
            x1 = __shfl_sync(0xffffffffu, u1, srcB);
            a[2] = odd ? x1 : x0;
            x0 = __shfl_sync(0xffffffffu, u2, srcB);
            x1 = __shfl_sync(0xffffffffu, u3, srcB);
            a[3] = odd ? x1 : x0;

            const int k0 = ks << 3;
#pragma unroll
            for (int nt = 0; nt < 8; ++nt) {
                uint32_t bfr[2];
                bfr[0] = Vb[(k0 + tg) * FV_STR + (nt << 3) + g];
                bfr[1] = Vb[(k0 + tg + 4) * FV_STR + (nt << 3) + g];
                mma_tf32(oacc[nt], a, bfr);
            }
        }
        __syncthreads();   // all warps done with this K/V buffer
    }

    // ---- epilogue: normalize, round to tf32 bits, write concat-head -------
    float inv0 = 1.f / l_r[0];
    float inv1 = 1.f / l_r[1];
    float* Og = g_att + (size_t)(b * T_ + t0) * C_ + h * D_;
    int row = m0 + g;
#pragma unroll
    for (int nt = 0; nt < 8; ++nt) {
        int col = (nt << 3) + (tg << 1);
        float2 o0, o1;
        o0.x = __uint_as_float(f2tf(oacc[nt][0] * inv0));
        o0.y = __uint_as_float(f2tf(oacc[nt][1] * inv0));
        o1.x = __uint_as_float(f2tf(oacc[nt][2] * inv1));
        o1.y = __uint_as_float(f2tf(oacc[nt][3] * inv1));
        *(float2*)(Og + (size_t)row * C_ + col)       = o0;
        *(float2*)(Og + (size_t)(row + 8) * C_ + col) = o1;
    }
}

// ---------------- launch ---------------------------------------------------
extern "C" void kernel_launch(void* const* d_in, const int* in_sizes, int n_in,
                              void* d_out, int out_size)
{
    const float* x  = (const float*)d_in[0];
    const float* wq = (const float*)d_in[1];
    const float* bq = (const float*)d_in[2];
    const float* wk = (const float*)d_in[3];
    const float* bk = (const float*)d_in[4];
    const float* wv = (const float*)d_in[5];
    const float* bv = (const float*)d_in[6];
    const float* wo = (const float*)d_in[7];
    const float* bo = (const float*)d_in[8];
    float* out = (float*)d_out;

    cudaFuncSetAttribute(qkv_kernel,
                         cudaFuncAttributeMaxDynamicSharedMemorySize, G_SMEM_BYTES);
    cudaFuncSetAttribute(out_kernel,
                         cudaFuncAttributeMaxDynamicSharedMemorySize, G_SMEM_BYTES);
    cudaFuncSetAttribute(flash_kernel,
                         cudaFuncAttributeMaxDynamicSharedMemorySize, FSMEM_BYTES);

    convx_kernel<<<BT_ * C_ / 4 / 256, 256>>>(x);
    convw_kernel<<<dim3(C_ * C_ / 4 / 256, 4), 256>>>(wq, wk, wv, wo);
    qkv_kernel<<<dim3(C_ / 128, BT_ / 128, 3), 256, G_SMEM_BYTES>>>(bq, bk, bv);
    flash_kernel<<<dim3(T_ / 128, B_ * H_), 256, FSMEM_BYTES>>>();
    out_kernel<<<dim3(C_ / 128, BT_ / 128), 256, G_SMEM_BYTES>>>(bo, out);
}

// round 7
// speedup vs baseline: 1.3478x; 1.0616x over previous
#include <cuda_runtime.h>
#include <cstdint>
#include <math.h>

#define B_  2
#define T_  2048
#define C_  1024
#define H_  16
#define D_  64
#define BT_ 4096

// ---------------- scratch (allocation-free contract: __device__ globals) ----
__device__ float g_q[BT_ * C_];
__device__ float g_k[BT_ * C_];
__device__ float g_v[BT_ * C_];
__device__ float g_att[BT_ * C_];          // tf32 bits after flash
__device__ float g_xt[BT_ * C_];           // x pre-rounded to tf32 bits
__device__ float g_wt[4 * C_ * C_];        // wq,wk,wv,wo pre-rounded

// ---------------- helpers ---------------------------------------------------
__device__ __forceinline__ uint32_t smem_u32(const void* p) {
    uint32_t a;
    asm("{ .reg .u64 t; cvta.to.shared.u64 t, %1; cvt.u32.u64 %0, t; }"
        : "=r"(a) : "l"(p));
    return a;
}

__device__ __forceinline__ uint32_t f2tf(float x) {
    uint32_t u;
    asm("cvt.rna.tf32.f32 %0, %1;" : "=r"(u) : "f"(x));
    return u;
}

__device__ __forceinline__ void mma_tf32(float c[4], const uint32_t a[4],
                                         const uint32_t b[2]) {
    asm volatile(
        "mma.sync.aligned.m16n8k8.row.col.f32.tf32.tf32.f32 "
        "{%0,%1,%2,%3}, {%4,%5,%6,%7}, {%8,%9}, {%0,%1,%2,%3};\n"
        : "+f"(c[0]), "+f"(c[1]), "+f"(c[2]), "+f"(c[3])
        : "r"(a[0]), "r"(a[1]), "r"(a[2]), "r"(a[3]),
          "r"(b[0]), "r"(b[1]));
}

__device__ __forceinline__ void cpa16(uint32_t saddr, const void* g) {
    asm volatile("cp.async.cg.shared.global [%0], [%1], 16;"
                 :: "r"(saddr), "l"(g) : "memory");
}
#define CP_COMMIT() asm volatile("cp.async.commit_group;" ::: "memory")
#define CP_WAIT1()  asm volatile("cp.async.wait_group 1;" ::: "memory")
#define CP_WAIT0()  asm volatile("cp.async.wait_group 0;" ::: "memory")

__device__ __forceinline__ void rope2(float& e, float& o, float t,
                                      float f0, float f1, float scale) {
    float s0, c0, s1, c1;
    sincosf(t * f0, &s0, &c0);
    sincosf(t * f1, &s1, &c1);
    float en = (e * c0 - o * s0) * scale;
    float on = (o * c1 + e * s1) * scale;
    e = en; o = on;
}

#define ROPE_LG 0.41524103786091404f   // log2(10000)*2/64

// ---------------- tf32 pre-convert kernels ---------------------------------
__global__ __launch_bounds__(256) void convx_kernel(const float* __restrict__ s)
{
    int i = blockIdx.x * 256 + threadIdx.x;        // over 1M float4
    float4 v = ((const float4*)s)[i];
    uint4 u = make_uint4(f2tf(v.x), f2tf(v.y), f2tf(v.z), f2tf(v.w));
    ((uint4*)g_xt)[i] = u;
}

__global__ __launch_bounds__(256) void convw_kernel(
    const float* __restrict__ wq, const float* __restrict__ wk,
    const float* __restrict__ wv, const float* __restrict__ wo)
{
    const float* src;
    int z = blockIdx.y;
    if (z == 0)      src = wq;
    else if (z == 1) src = wk;
    else if (z == 2) src = wv;
    else             src = wo;
    int i = blockIdx.x * 256 + threadIdx.x;        // over 256K float4
    float4 v = ((const float4*)src)[i];
    uint4 u = make_uint4(f2tf(v.x), f2tf(v.y), f2tf(v.z), f2tf(v.w));
    ((uint4*)(g_wt + (size_t)z * C_ * C_))[i] = u;
}

// ---------------- tf32 GEMM: C[M,N] = A[M,K] @ W[N,K]^T + bias --------------
// A and W hold tf32 bits already. block 128x128, BK=32, 256 threads = 8 warps
// (warp tile 32m x 64n). cp.async double buffer, stride 36 (conflict-free).
#define GSTR 36
#define G_STAGE_W (2 * 128 * GSTR)        // A+B words per stage = 9216
#define G_SMEM_BYTES (2 * G_STAGE_W * 4)  // 73728

__device__ __forceinline__ void gemm_tf32_body(
    const float* __restrict__ A, const float* __restrict__ W,
    const float* __restrict__ bias, float* __restrict__ Cm,
    int bx, int by, int mode)
{
    extern __shared__ uint32_t gsm[];

    const int K = C_, N = C_;
    const int tid  = threadIdx.x;
    const int warp = tid >> 5;
    const int lane = tid & 31;
    const int g    = lane >> 2;
    const int tg   = lane & 3;
    const int m0   = (warp & 3) * 32;
    const int n0   = (warp >> 2) * 64;
    const int bm   = by * 128;
    const int bn   = bx * 128;

    const uint32_t smem_base = smem_u32(gsm);
    const float* Ap = A + (size_t)bm * K;
    const float* Wp = W + (size_t)bn * K;

    float acc[2][8][4];
#pragma unroll
    for (int mt = 0; mt < 2; ++mt)
#pragma unroll
        for (int nt = 0; nt < 8; ++nt)
#pragma unroll
            for (int i = 0; i < 4; ++i) acc[mt][nt][i] = 0.f;

    auto issue = [&](int kb) {
        const int buf = kb & 1;
        uint32_t sa = smem_base + (buf * G_STAGE_W) * 4;
        uint32_t sb = sa + 128 * GSTR * 4;
        const float* Ak = Ap + kb * 32;
        const float* Wk = Wp + kb * 32;
#pragma unroll
        for (int i = 0; i < 4; ++i) {
            int id = tid + (i << 8);
            int r  = id >> 3;
            int cw = (id & 7) << 2;
            cpa16(sa + (r * GSTR + cw) * 4, Ak + (size_t)r * K + cw);
            cpa16(sb + (r * GSTR + cw) * 4, Wk + (size_t)r * K + cw);
        }
    };

    issue(0);
    CP_COMMIT();

    const int NKB = K / 32;   // 32
    for (int kb = 0; kb < NKB; ++kb) {
        if (kb + 1 < NKB) {
            issue(kb + 1);
            CP_COMMIT();
            CP_WAIT1();
        } else {
            CP_WAIT0();
        }
        __syncthreads();

        const uint32_t* As = gsm + (kb & 1) * G_STAGE_W;
        const uint32_t* Bs = As + 128 * GSTR;

#pragma unroll
        for (int ks = 0; ks < 4; ++ks) {
            const int k0 = ks * 8;
            uint32_t a[2][4], b[8][2];
#pragma unroll
            for (int mt = 0; mt < 2; ++mt) {
                int row = m0 + mt * 16 + g;
                a[mt][0] = As[row * GSTR + k0 + tg];
                a[mt][1] = As[(row + 8) * GSTR + k0 + tg];
                a[mt][2] = As[row * GSTR + k0 + tg + 4];
                a[mt][3] = As[(row + 8) * GSTR + k0 + tg + 4];
            }
#pragma unroll
            for (int nt = 0; nt < 8; ++nt) {
                int rn = n0 + nt * 8 + g;
                b[nt][0] = Bs[rn * GSTR + k0 + tg];
                b[nt][1] = Bs[rn * GSTR + k0 + tg + 4];
            }
#pragma unroll
            for (int mt = 0; mt < 2; ++mt)
#pragma unroll
                for (int nt = 0; nt < 8; ++nt)
                    mma_tf32(acc[mt][nt], a[mt], b[nt]);
        }
        __syncthreads();
    }

    // ---- epilogue: bias (+ optional rope/scale/round), write --------------
    const bool do_rope = (mode == 1 || mode == 2);
    const float rscale = (mode == 1) ? 0.125f : 1.f;
#pragma unroll
    for (int nt = 0; nt < 8; ++nt) {
        int col = bn + n0 + nt * 8 + (tg << 1);
        float2 bv = *(const float2*)(bias + col);
        float f0 = 0.f, f1 = 0.f;
        if (do_rope) {
            int d0 = col & (D_ - 1);
            f0 = exp2f(-ROPE_LG * (float)(d0 & 31));
            f1 = exp2f(-ROPE_LG * (float)((d0 + 1) & 31));
        }
#pragma unroll
        for (int mt = 0; mt < 2; ++mt) {
            int row = bm + m0 + mt * 16 + g;
            float e0 = acc[mt][nt][0] + bv.x, o0 = acc[mt][nt][1] + bv.y;
            float e1 = acc[mt][nt][2] + bv.x, o1 = acc[mt][nt][3] + bv.y;
            if (do_rope) {
                rope2(e0, o0, (float)(row & (T_ - 1)), f0, f1, rscale);
                rope2(e1, o1, (float)((row + 8) & (T_ - 1)), f0, f1, rscale);
            }
            float2 w0, w1;
            if (mode != 0) {
                w0.x = __uint_as_float(f2tf(e0));
                w0.y = __uint_as_float(f2tf(o0));
                w1.x = __uint_as_float(f2tf(e1));
                w1.y = __uint_as_float(f2tf(o1));
            } else {
                w0.x = e0; w0.y = o0;
                w1.x = e1; w1.y = o1;
            }
            *(float2*)(Cm + (size_t)row * N + col)       = w0;
            *(float2*)(Cm + (size_t)(row + 8) * N + col) = w1;
        }
    }
}

__global__ __launch_bounds__(256, 2) void qkv_kernel(
    const float* __restrict__ bq, const float* __restrict__ bk,
    const float* __restrict__ bv)
{
    const float* bb; float* out; int mode;
    int z = blockIdx.z;
    if (z == 0)      { bb = bq; out = g_q; mode = 1; }
    else if (z == 1) { bb = bk; out = g_k; mode = 2; }
    else             { bb = bv; out = g_v; mode = 3; }
    gemm_tf32_body(g_xt, g_wt + (size_t)z * C_ * C_, bb, out,
                   blockIdx.x, blockIdx.y, mode);
}

__global__ __launch_bounds__(256, 2) void out_kernel(
    const float* __restrict__ bo, float* __restrict__ out)
{
    gemm_tf32_body(g_att, g_wt + (size_t)3 * C_ * C_, bo, out,
                   blockIdx.x, blockIdx.y, 0);
}

// ---------------- flash attention (tf32 warp-mma, Br=256, Bc=64) -----------
// 256 threads = 8 warps, each warp owns 32 q-rows (mt=2): every K/V fragment
// feeds 2 MMAs. K/V double-buffered via cp.async; PV A-fragments via shuffle.
// smem = Q(256x68) + 2 stages of K(64x68)+V(64x72) = 35328 words = 141312 B.
#define FQ_STR 68
#define FK_STR 68
#define FV_STR 72
#define FL_QS   0
#define FL_KV   (256 * FQ_STR)                       // 17408
#define FL_STAGE_W (64 * FK_STR + 64 * FV_STR)       // 8960
#define FL_WORDS (FL_KV + 2 * FL_STAGE_W)            // 35328
#define FSMEM_BYTES (FL_WORDS * 4)                   // 141312

__global__ __launch_bounds__(256) void flash_kernel()
{
    extern __shared__ uint32_t sm[];
    uint32_t* Qs = sm + FL_QS;

    const int bh = blockIdx.y;
    const int b  = bh >> 4;
    const int h  = bh & 15;
    const int t0 = blockIdx.x << 8;                  // 256 q-rows per CTA
    const int tid  = threadIdx.x;
    const int warp = tid >> 5;
    const int lane = tid & 31;
    const int g    = lane >> 2;
    const int tg   = lane & 3;
    const int m0   = warp << 5;                      // warp's 32-row base

    const uint32_t smem_base = smem_u32(sm);
    const float* Kg0 = g_k + (size_t)(b * T_) * C_ + h * D_;
    const float* Vg0 = g_v + (size_t)(b * T_) * C_ + h * D_;

    auto issue_kv = [&](int kt) {
        const int buf = kt & 1;
        const uint32_t ks_base = smem_base + (FL_KV + buf * FL_STAGE_W) * 4;
        const uint32_t vs_base = ks_base + 64 * FK_STR * 4;
        const float* Kg = Kg0 + (size_t)(kt << 6) * C_;
        const float* Vg = Vg0 + (size_t)(kt << 6) * C_;
#pragma unroll
        for (int i = 0; i < 4; ++i) {
            int f = tid + (i << 8);
            int r = f >> 4, c = (f & 15) << 2;
            cpa16(ks_base + (r * FK_STR + c) * 4, Kg + (size_t)r * C_ + c);
            cpa16(vs_base + (r * FV_STR + c) * 4, Vg + (size_t)r * C_ + c);
        }
    };

    issue_kv(0);
    CP_COMMIT();

    // ---- load Q block (256 rows); bits already tf32 ----
    const float* Qg = g_q + (size_t)(b * T_ + t0) * C_ + h * D_;
#pragma unroll
    for (int it = 0; it < 16; ++it) {
        int f = tid + (it << 8);
        int r = f >> 4, c = (f & 15) << 2;
        float4 v = *(const float4*)(Qg + (size_t)r * C_ + c);
        float* p = (float*)&Qs[r * FQ_STR + c];
        *(float2*)p       = make_float2(v.x, v.y);
        *(float2*)(p + 2) = make_float2(v.z, v.w);
    }

    float oacc[2][8][4];
    float m_r[4], l_r[4];
#pragma unroll
    for (int mt = 0; mt < 2; ++mt)
#pragma unroll
        for (int nt = 0; nt < 8; ++nt)
#pragma unroll
            for (int i = 0; i < 4; ++i) oacc[mt][nt][i] = 0.f;
#pragma unroll
    for (int i = 0; i < 4; ++i) { m_r[i] = -1e30f; l_r[i] = 0.f; }

    const int srcA = (lane & 28) | (tg >> 1);
    const int srcB = srcA | 2;
    const bool odd = (tg & 1);

    const int NKT = T_ / 64;   // 32
    for (int kt = 0; kt < NKT; ++kt) {
        if (kt + 1 < NKT) {
            issue_kv(kt + 1);
            CP_COMMIT();
            CP_WAIT1();
        } else {
            CP_WAIT0();
        }
        __syncthreads();

        const uint32_t* Kb = sm + FL_KV + (kt & 1) * FL_STAGE_W;
        const uint32_t* Vb = Kb + 64 * FK_STR;

        // ---- S = Q @ K^T ----
        float sacc[2][8][4];
#pragma unroll
        for (int mt = 0; mt < 2; ++mt)
#pragma unroll
            for (int nt = 0; nt < 8; ++nt)
#pragma unroll
                for (int i = 0; i < 4; ++i) sacc[mt][nt][i] = 0.f;

#pragma unroll
        for (int ks = 0; ks < 8; ++ks) {
            const int k0 = ks << 3;
            uint32_t a[2][4];
#pragma unroll
            for (int mt = 0; mt < 2; ++mt) {
                int row = m0 + mt * 16 + g;
                a[mt][0] = Qs[row * FQ_STR + k0 + tg];
                a[mt][1] = Qs[(row + 8) * FQ_STR + k0 + tg];
                a[mt][2] = Qs[row * FQ_STR + k0 + tg + 4];
                a[mt][3] = Qs[(row + 8) * FQ_STR + k0 + tg + 4];
            }
#pragma unroll
            for (int nt = 0; nt < 8; ++nt) {
                uint32_t bfr[2];
                int rn = (nt << 3) + g;
                bfr[0] = Kb[rn * FK_STR + k0 + tg];
                bfr[1] = Kb[rn * FK_STR + k0 + tg + 4];
                mma_tf32(sacc[0][nt], a[0], bfr);
                mma_tf32(sacc[1][nt], a[1], bfr);
            }
        }

        // ---- online softmax (4 row-groups: mt*16 + {g, g+8}) ----
        float corr[2][2];
#pragma unroll
        for (int mt = 0; mt < 2; ++mt) {
            float mx0 = -1e30f, mx1 = -1e30f;
#pragma unroll
            for (int nt = 0; nt < 8; ++nt) {
                mx0 = fmaxf(mx0, fmaxf(sacc[mt][nt][0], sacc[mt][nt][1]));
                mx1 = fmaxf(mx1, fmaxf(sacc[mt][nt][2], sacc[mt][nt][3]));
            }
            mx0 = fmaxf(mx0, __shfl_xor_sync(0xffffffffu, mx0, 1));
            mx0 = fmaxf(mx0, __shfl_xor_sync(0xffffffffu, mx0, 2));
            mx1 = fmaxf(mx1, __shfl_xor_sync(0xffffffffu, mx1, 1));
            mx1 = fmaxf(mx1, __shfl_xor_sync(0xffffffffu, mx1, 2));

            float mn0 = fmaxf(m_r[mt * 2 + 0], mx0);
            float mn1 = fmaxf(m_r[mt * 2 + 1], mx1);
            corr[mt][0] = __expf(m_r[mt * 2 + 0] - mn0);
            corr[mt][1] = __expf(m_r[mt * 2 + 1] - mn1);

            float rs0 = 0.f, rs1 = 0.f;
#pragma unroll
            for (int nt = 0; nt < 8; ++nt) {
                float p0 = __expf(sacc[mt][nt][0] - mn0);
                float p1 = __expf(sacc[mt][nt][1] - mn0);
                float p2 = __expf(sacc[mt][nt][2] - mn1);
                float p3 = __expf(sacc[mt][nt][3] - mn1);
                rs0 += p0 + p1;
                rs1 += p2 + p3;
                sacc[mt][nt][0] = p0; sacc[mt][nt][1] = p1;
                sacc[mt][nt][2] = p2; sacc[mt][nt][3] = p3;
            }
            rs0 += __shfl_xor_sync(0xffffffffu, rs0, 1);
            rs0 += __shfl_xor_sync(0xffffffffu, rs0, 2);
            rs1 += __shfl_xor_sync(0xffffffffu, rs1, 1);
            rs1 += __shfl_xor_sync(0xffffffffu, rs1, 2);

            l_r[mt * 2 + 0] = l_r[mt * 2 + 0] * corr[mt][0] + rs0;
            l_r[mt * 2 + 1] = l_r[mt * 2 + 1] * corr[mt][1] + rs1;
            m_r[mt * 2 + 0] = mn0;
            m_r[mt * 2 + 1] = mn1;

#pragma unroll
            for (int nt = 0; nt < 8; ++nt) {
                oacc[mt][nt][0] *= corr[mt][0]; oacc[mt][nt][1] *= corr[mt][0];
                oacc[mt][nt][2] *= corr[mt][1]; oacc[mt][nt][3] *= corr[mt][1];
            }
        }

        // ---- O += P @ V, A-fragments via shuffles (no smem round-trip) ----
#pragma unroll
        for (int ks = 0; ks < 8; ++ks) {
            uint32_t a[2][4];
#pragma unroll
            for (int mt = 0; mt < 2; ++mt) {
                uint32_t u0 = f2tf(sacc[mt][ks][0]);
                uint32_t u1 = f2tf(sacc[mt][ks][1]);
                uint32_t u2 = f2tf(sacc[mt][ks][2]);
                uint32_t u3 = f2tf(sacc[mt][ks][3]);
                uint32_t x0, x1;
                x0 = __shfl_sync(0xffffffffu, u0, srcA);
                x1 = __shfl_sync(0xffffffffu, u1, srcA);
                a[mt][0] = odd ? x1 : x0;
                x0 = __shfl_sync(0xffffffffu, u2, srcA);
                x1 = __shfl_sync(0xffffffffu, u3, srcA);
                a[mt][1] = odd ? x1 : x0;
                x0 = __shfl_sync(0xffffffffu, u0, srcB);
                x1 = __shfl_sync(0xffffffffu, u1, srcB);
                a[mt][2] = odd ? x1 : x0;
                x0 = __shfl_sync(0xffffffffu, u2, srcB);
                x1 = __shfl_sync(0xffffffffu, u3, srcB);
                a[mt][3] = odd ? x1 : x0;
            }

            const int k0 = ks << 3;
#pragma unroll
            for (int nt = 0; nt < 8; ++nt) {
                uint32_t bfr[2];
                bfr[0] = Vb[(k0 + tg) * FV_STR + (nt << 3) + g];
                bfr[1] = Vb[(k0 + tg + 4) * FV_STR + (nt << 3) + g];
                mma_tf32(oacc[0][nt], a[0], bfr);
                mma_tf32(oacc[1][nt], a[1], bfr);
            }
        }
        __syncthreads();   // all warps done with this K/V buffer
    }

    // ---- epilogue: normalize, round to tf32 bits, write concat-head -------
    float* Og = g_att + (size_t)(b * T_ + t0) * C_ + h * D_;
#pragma unroll
    for (int mt = 0; mt < 2; ++mt) {
        float inv0 = 1.f / l_r[mt * 2 + 0];
        float inv1 = 1.f / l_r[mt * 2 + 1];
        int row = m0 + mt * 16 + g;
#pragma unroll
        for (int nt = 0; nt < 8; ++nt) {
            int col = (nt << 3) + (tg << 1);
            float2 o0, o1;
            o0.x = __uint_as_float(f2tf(oacc[mt][nt][0] * inv0));
            o0.y = __uint_as_float(f2tf(oacc[mt][nt][1] * inv0));
            o1.x = __uint_as_float(f2tf(oacc[mt][nt][2] * inv1));
            o1.y = __uint_as_float(f2tf(oacc[mt][nt][3] * inv1));
            *(float2*)(Og + (size_t)row * C_ + col)       = o0;
            *(float2*)(Og + (size_t)(row + 8) * C_ + col) = o1;
        }
    }
}

// ---------------- launch ---------------------------------------------------
extern "C" void kernel_launch(void* const* d_in, const int* in_sizes, int n_in,
                              void* d_out, int out_size)
{
    const float* x  = (const float*)d_in[0];
    const float* wq = (const float*)d_in[1];
    const float* bq = (const float*)d_in[2];
    const float* wk = (const float*)d_in[3];
    const float* bk = (const float*)d_in[4];
    const float* wv = (const float*)d_in[5];
    const float* bv = (const float*)d_in[6];
    const float* wo = (const float*)d_in[7];
    const float* bo = (const float*)d_in[8];
    float* out = (float*)d_out;

    cudaFuncSetAttribute(qkv_kernel,
                         cudaFuncAttributeMaxDynamicSharedMemorySize, G_SMEM_BYTES);
    cudaFuncSetAttribute(out_kernel,
                         cudaFuncAttributeMaxDynamicSharedMemorySize, G_SMEM_BYTES);
    cudaFuncSetAttribute(flash_kernel,
                         cudaFuncAttributeMaxDynamicSharedMemorySize, FSMEM_BYTES);

    convx_kernel<<<BT_ * C_ / 4 / 256, 256>>>(x);
    convw_kernel<<<dim3(C_ * C_ / 4 / 256, 4), 256>>>(wq, wk, wv, wo);
    qkv_kernel<<<dim3(C_ / 128, BT_ / 128, 3), 256, G_SMEM_BYTES>>>(bq, bk, bv);
    flash_kernel<<<dim3(T_ / 256, B_ * H_), 256, FSMEM_BYTES>>>();
    out_kernel<<<dim3(C_ / 128, BT_ / 128), 256, G_SMEM_BYTES>>>(bo, out);
}

// round 8
// speedup vs baseline: 1.7232x; 1.2785x over previous
#include <cuda_runtime.h>
#include <cuda_fp16.h>
#include <cstdint>
#include <math.h>

#define B_  2
#define T_  2048
#define C_  1024
#define H_  16
#define D_  64
#define BT_ 4096

// ---------------- scratch (allocation-free contract: __device__ globals) ----
__device__ __half g_qh[BT_ * C_];          // Q fp16 (rope+scale*log2e applied)
__device__ __half g_kh[BT_ * C_];          // K fp16 (rope applied)
__device__ __half g_vt[B_ * H_ * D_ * T_]; // V fp16 transposed [b][h][d][t]
__device__ float  g_att[BT_ * C_];         // tf32 bits after flash
__device__ float  g_xt[BT_ * C_];          // x pre-rounded to tf32 bits
__device__ float  g_wt[4 * C_ * C_];       // wq,wk,wv,wo pre-rounded

// ---------------- helpers ---------------------------------------------------
__device__ __forceinline__ uint32_t smem_u32(const void* p) {
    uint32_t a;
    asm("{ .reg .u64 t; cvta.to.shared.u64 t, %1; cvt.u32.u64 %0, t; }"
        : "=r"(a) : "l"(p));
    return a;
}

__device__ __forceinline__ uint32_t f2tf(float x) {
    uint32_t u;
    asm("cvt.rna.tf32.f32 %0, %1;" : "=r"(u) : "f"(x));
    return u;
}

__device__ __forceinline__ float ex2f(float x) {
    float r;
    asm("ex2.approx.ftz.f32 %0, %1;" : "=f"(r) : "f"(x));
    return r;
}

__device__ __forceinline__ uint32_t packh2(float lo, float hi) {
    __half2 t = __floats2half2_rn(lo, hi);
    return *(uint32_t*)&t;
}

__device__ __forceinline__ void mma_tf32(float c[4], const uint32_t a[4],
                                         const uint32_t b[2]) {
    asm volatile(
        "mma.sync.aligned.m16n8k8.row.col.f32.tf32.tf32.f32 "
        "{%0,%1,%2,%3}, {%4,%5,%6,%7}, {%8,%9}, {%0,%1,%2,%3};\n"
        : "+f"(c[0]), "+f"(c[1]), "+f"(c[2]), "+f"(c[3])
        : "r"(a[0]), "r"(a[1]), "r"(a[2]), "r"(a[3]),
          "r"(b[0]), "r"(b[1]));
}

__device__ __forceinline__ void mma_f16(float c[4], const uint32_t a[4],
                                        uint32_t b0, uint32_t b1) {
    asm volatile(
        "mma.sync.aligned.m16n8k16.row.col.f32.f16.f16.f32 "
        "{%0,%1,%2,%3}, {%4,%5,%6,%7}, {%8,%9}, {%0,%1,%2,%3};\n"
        : "+f"(c[0]), "+f"(c[1]), "+f"(c[2]), "+f"(c[3])
        : "r"(a[0]), "r"(a[1]), "r"(a[2]), "r"(a[3]),
          "r"(b0), "r"(b1));
}

__device__ __forceinline__ void cpa16(uint32_t saddr, const void* g) {
    asm volatile("cp.async.cg.shared.global [%0], [%1], 16;"
                 :: "r"(saddr), "l"(g) : "memory");
}
#define CP_COMMIT() asm volatile("cp.async.commit_group;" ::: "memory")
#define CP_WAIT1()  asm volatile("cp.async.wait_group 1;" ::: "memory")
#define CP_WAIT0()  asm volatile("cp.async.wait_group 0;" ::: "memory")

__device__ __forceinline__ void rope2(float& e, float& o, float t,
                                      float f0, float f1, float scale) {
    float s0, c0, s1, c1;
    sincosf(t * f0, &s0, &c0);
    sincosf(t * f1, &s1, &c1);
    float en = (e * c0 - o * s0) * scale;
    float on = (o * c1 + e * s1) * scale;
    e = en; o = on;
}

#define ROPE_LG 0.41524103786091404f   // log2(10000)*2/64
#define QSCALE  0.18033688011112042f   // 0.125 * log2(e)

// ---------------- tf32 pre-convert kernels ---------------------------------
__global__ __launch_bounds__(256) void convx_kernel(const float* __restrict__ s)
{
    int i = blockIdx.x * 256 + threadIdx.x;
    float4 v = ((const float4*)s)[i];
    uint4 u = make_uint4(f2tf(v.x), f2tf(v.y), f2tf(v.z), f2tf(v.w));
    ((uint4*)g_xt)[i] = u;
}

__global__ __launch_bounds__(256) void convw_kernel(
    const float* __restrict__ wq, const float* __restrict__ wk,
    const float* __restrict__ wv, const float* __restrict__ wo)
{
    const float* src;
    int z = blockIdx.y;
    if (z == 0)      src = wq;
    else if (z == 1) src = wk;
    else if (z == 2) src = wv;
    else             src = wo;
    int i = blockIdx.x * 256 + threadIdx.x;
    float4 v = ((const float4*)src)[i];
    uint4 u = make_uint4(f2tf(v.x), f2tf(v.y), f2tf(v.z), f2tf(v.w));
    ((uint4*)(g_wt + (size_t)z * C_ * C_))[i] = u;
}

// ---------------- tf32 GEMM: C[M,N] = A[M,K] @ W[N,K]^T + bias --------------
// block 128x128, BK=32, 256 threads, cp.async double buffer, stride 36.
// mode: 0 = fp32 out, 1 = Q->fp16 rope, 2 = K->fp16 rope, 3 = V->fp16 transp.
#define GSTR 36
#define G_STAGE_W (2 * 128 * GSTR)
#define G_SMEM_BYTES (2 * G_STAGE_W * 4)

__device__ __forceinline__ void gemm_tf32_body(
    const float* __restrict__ A, const float* __restrict__ W,
    const float* __restrict__ bias, float* __restrict__ Cm,
    int bx, int by, int mode)
{
    extern __shared__ uint32_t gsm[];

    const int K = C_, N = C_;
    const int tid  = threadIdx.x;
    const int warp = tid >> 5;
    const int lane = tid & 31;
    const int g    = lane >> 2;
    const int tg   = lane & 3;
    const int m0   = (warp & 3) * 32;
    const int n0   = (warp >> 2) * 64;
    const int bm   = by * 128;
    const int bn   = bx * 128;

    const uint32_t smem_base = smem_u32(gsm);
    const float* Ap = A + (size_t)bm * K;
    const float* Wp = W + (size_t)bn * K;

    float acc[2][8][4];
#pragma unroll
    for (int mt = 0; mt < 2; ++mt)
#pragma unroll
        for (int nt = 0; nt < 8; ++nt)
#pragma unroll
            for (int i = 0; i < 4; ++i) acc[mt][nt][i] = 0.f;

    auto issue = [&](int kb) {
        const int buf = kb & 1;
        uint32_t sa = smem_base + (buf * G_STAGE_W) * 4;
        uint32_t sb = sa + 128 * GSTR * 4;
        const float* Ak = Ap + kb * 32;
        const float* Wk = Wp + kb * 32;
#pragma unroll
        for (int i = 0; i < 4; ++i) {
            int id = tid + (i << 8);
            int r  = id >> 3;
            int cw = (id & 7) << 2;
            cpa16(sa + (r * GSTR + cw) * 4, Ak + (size_t)r * K + cw);
            cpa16(sb + (r * GSTR + cw) * 4, Wk + (size_t)r * K + cw);
        }
    };

    issue(0);
    CP_COMMIT();

    const int NKB = K / 32;
    for (int kb = 0; kb < NKB; ++kb) {
        if (kb + 1 < NKB) {
            issue(kb + 1);
            CP_COMMIT();
            CP_WAIT1();
        } else {
            CP_WAIT0();
        }
        __syncthreads();

        const uint32_t* As = gsm + (kb & 1) * G_STAGE_W;
        const uint32_t* Bs = As + 128 * GSTR;

#pragma unroll
        for (int ks = 0; ks < 4; ++ks) {
            const int k0 = ks * 8;
            uint32_t a[2][4], b[8][2];
#pragma unroll
            for (int mt = 0; mt < 2; ++mt) {
                int row = m0 + mt * 16 + g;
                a[mt][0] = As[row * GSTR + k0 + tg];
                a[mt][1] = As[(row + 8) * GSTR + k0 + tg];
                a[mt][2] = As[row * GSTR + k0 + tg + 4];
                a[mt][3] = As[(row + 8) * GSTR + k0 + tg + 4];
            }
#pragma unroll
            for (int nt = 0; nt < 8; ++nt) {
                int rn = n0 + nt * 8 + g;
                b[nt][0] = Bs[rn * GSTR + k0 + tg];
                b[nt][1] = Bs[rn * GSTR + k0 + tg + 4];
            }
#pragma unroll
            for (int mt = 0; mt < 2; ++mt)
#pragma unroll
                for (int nt = 0; nt < 8; ++nt)
                    mma_tf32(acc[mt][nt], a[mt], b[nt]);
        }
        __syncthreads();
    }

    // ---- epilogue ----------------------------------------------------------
    const bool do_rope = (mode == 1 || mode == 2);
    const float rscale = (mode == 1) ? QSCALE : 1.f;
#pragma unroll
    for (int nt = 0; nt < 8; ++nt) {
        int col = bn + n0 + nt * 8 + (tg << 1);
        float2 bv = *(const float2*)(bias + col);
        float f0 = 0.f, f1 = 0.f;
        if (do_rope) {
            int d0 = col & (D_ - 1);
            f0 = exp2f(-ROPE_LG * (float)(d0 & 31));
            f1 = exp2f(-ROPE_LG * (float)((d0 + 1) & 31));
        }
#pragma unroll
        for (int mt = 0; mt < 2; ++mt) {
            int row = bm + m0 + mt * 16 + g;
            float e0 = acc[mt][nt][0] + bv.x, o0 = acc[mt][nt][1] + bv.y;
            float e1 = acc[mt][nt][2] + bv.x, o1 = acc[mt][nt][3] + bv.y;
            if (do_rope) {
                rope2(e0, o0, (float)(row & (T_ - 1)), f0, f1, rscale);
                rope2(e1, o1, (float)((row + 8) & (T_ - 1)), f0, f1, rscale);
            }
            if (mode == 1 || mode == 2) {
                __half* dst = (mode == 1 ? g_qh : g_kh);
                *(__half2*)(dst + (size_t)row * N + col) =
                    __floats2half2_rn(e0, o0);
                *(__half2*)(dst + (size_t)(row + 8) * N + col) =
                    __floats2half2_rn(e1, o1);
            } else if (mode == 3) {
                int h = col >> 6, d = col & 63;
                int b = row >> 11;
                int t = row & (T_ - 1);
                __half* base = g_vt + ((size_t)(b * H_ + h) * D_) * T_;
                base[(size_t)d * T_ + t]            = __float2half_rn(e0);
                base[(size_t)(d + 1) * T_ + t]      = __float2half_rn(o0);
                base[(size_t)d * T_ + t + 8]        = __float2half_rn(e1);
                base[(size_t)(d + 1) * T_ + t + 8]  = __float2half_rn(o1);
            } else {
                *(float2*)(Cm + (size_t)row * N + col)       = make_float2(e0, o0);
                *(float2*)(Cm + (size_t)(row + 8) * N + col) = make_float2(e1, o1);
            }
        }
    }
}

__global__ __launch_bounds__(256, 2) void qkv_kernel(
    const float* __restrict__ bq, const float* __restrict__ bk,
    const float* __restrict__ bv)
{
    const float* bb; int mode;
    int z = blockIdx.z;
    if (z == 0)      { bb = bq; mode = 1; }
    else if (z == 1) { bb = bk; mode = 2; }
    else             { bb = bv; mode = 3; }
    gemm_tf32_body(g_xt, g_wt + (size_t)z * C_ * C_, bb, nullptr,
                   blockIdx.x, blockIdx.y, mode);
}

__global__ __launch_bounds__(256, 2) void out_kernel(
    const float* __restrict__ bo, float* __restrict__ out)
{
    gemm_tf32_body(g_att, g_wt + (size_t)3 * C_ * C_, bo, out,
                   blockIdx.x, blockIdx.y, 0);
}

// ---------------- flash attention (fp16 m16n8k16, Br=256, Bc=64) -----------
// 256 threads = 8 warps, each warp 32 q-rows (mt=2). Q fragments cached in
// registers (kt-invariant). K [key][d] and V-transposed [d][key] tiles in
// smem via cp.async (fp16, 72-half rows = conflict-free 4g+tg pattern).
// PV A-fragments come directly from S C-fragments (FA2 identity) - no smem,
// no shuffles. Softmax in log2 domain (scale folded into Q).
#define FSTR_W 36                           // 72 halfs = 144B per row
#define F_STAGE_W (2 * 64 * FSTR_W)         // K+V words per stage = 4608
#define FSMEM_BYTES (2 * F_STAGE_W * 4)     // 36864

__global__ __launch_bounds__(256) void flash_kernel()
{
    extern __shared__ uint32_t sm[];

    const int bh = blockIdx.y;
    const int b  = bh >> 4;
    const int h  = bh & 15;
    const int t0 = blockIdx.x << 8;
    const int tid  = threadIdx.x;
    const int warp = tid >> 5;
    const int lane = tid & 31;
    const int g    = lane >> 2;
    const int tg   = lane & 3;
    const int m0   = warp << 5;

    const uint32_t smem_base = smem_u32(sm);
    const __half* Kg0 = g_kh + (size_t)(b * T_) * C_ + h * D_;
    const __half* Vt0 = g_vt + (size_t)(b * H_ + h) * D_ * T_;

    auto issue_kv = [&](int kt) {
        const int buf = kt & 1;
        const uint32_t kb = smem_base + (buf * F_STAGE_W) * 4;
        const uint32_t vb = kb + 64 * FSTR_W * 4;
#pragma unroll
        for (int i = 0; i < 2; ++i) {
            int id = tid + (i << 8);
            int r  = id >> 3;
            int c  = id & 7;                 // 16B chunk index
            cpa16(kb + (r * FSTR_W + c * 4) * 4,
                  Kg0 + (size_t)(kt * 64 + r) * C_ + c * 8);
            cpa16(vb + (r * FSTR_W + c * 4) * 4,
                  Vt0 + (size_t)r * T_ + kt * 64 + c * 8);
        }
    };

    issue_kv(0);
    CP_COMMIT();

    // ---- Q fragments, kt-invariant, direct from gmem into registers ------
    uint32_t qa[4][2][4];
    const __half* Qg = g_qh + (size_t)(b * T_ + t0 + m0) * C_ + h * D_;
#pragma unroll
    for (int ks = 0; ks < 4; ++ks)
#pragma unroll
        for (int mt = 0; mt < 2; ++mt) {
            const __half* p0 = Qg + (size_t)(mt * 16 + g) * C_ + 16 * ks + 2 * tg;
            const __half* p1 = p0 + 8 * C_;
            qa[ks][mt][0] = *(const uint32_t*)p0;
            qa[ks][mt][1] = *(const uint32_t*)p1;
            qa[ks][mt][2] = *(const uint32_t*)(p0 + 8);
            qa[ks][mt][3] = *(const uint32_t*)(p1 + 8);
        }

    float oacc[2][8][4];
    float m_r[4], l_r[4];
#pragma unroll
    for (int mt = 0; mt < 2; ++mt)
#pragma unroll
        for (int nt = 0; nt < 8; ++nt)
#pragma unroll
            for (int i = 0; i < 4; ++i) oacc[mt][nt][i] = 0.f;
#pragma unroll
    for (int i = 0; i < 4; ++i) { m_r[i] = -1e30f; l_r[i] = 0.f; }

    const int NKT = T_ / 64;   // 32
    for (int kt = 0; kt < NKT; ++kt) {
        if (kt + 1 < NKT) {
            issue_kv(kt + 1);
            CP_COMMIT();
            CP_WAIT1();
        } else {
            CP_WAIT0();
        }
        __syncthreads();

        const uint32_t* Kb = sm + (kt & 1) * F_STAGE_W;
        const uint32_t* Vb = Kb + 64 * FSTR_W;

        // ---- S = Q @ K^T (log2-scaled) ----
        float sacc[2][8][4];
#pragma unroll
        for (int mt = 0; mt < 2; ++mt)
#pragma unroll
            for (int nt = 0; nt < 8; ++nt)
#pragma unroll
                for (int i = 0; i < 4; ++i) sacc[mt][nt][i] = 0.f;

#pragma unroll
        for (int ks = 0; ks < 4; ++ks) {
#pragma unroll
            for (int nt = 0; nt < 8; ++nt) {
                int base = (nt * 8 + g) * FSTR_W + 8 * ks + tg;
                uint32_t b0 = Kb[base];
                uint32_t b1 = Kb[base + 4];
                mma_f16(sacc[0][nt], qa[ks][0], b0, b1);
                mma_f16(sacc[1][nt], qa[ks][1], b0, b1);
            }
        }

        // ---- online softmax (log2 domain) + pack P to fp16 A-fragments ----
        uint32_t pa[4][2][4];
#pragma unroll
        for (int mt = 0; mt < 2; ++mt) {
            float mx0 = -1e30f, mx1 = -1e30f;
#pragma unroll
            for (int nt = 0; nt < 8; ++nt) {
                mx0 = fmaxf(mx0, fmaxf(sacc[mt][nt][0], sacc[mt][nt][1]));
                mx1 = fmaxf(mx1, fmaxf(sacc[mt][nt][2], sacc[mt][nt][3]));
            }
            mx0 = fmaxf(mx0, __shfl_xor_sync(0xffffffffu, mx0, 1));
            mx0 = fmaxf(mx0, __shfl_xor_sync(0xffffffffu, mx0, 2));
            mx1 = fmaxf(mx1, __shfl_xor_sync(0xffffffffu, mx1, 1));
            mx1 = fmaxf(mx1, __shfl_xor_sync(0xffffffffu, mx1, 2));

            float mn0 = fmaxf(m_r[mt * 2 + 0], mx0);
            float mn1 = fmaxf(m_r[mt * 2 + 1], mx1);
            float corr0 = ex2f(m_r[mt * 2 + 0] - mn0);
            float corr1 = ex2f(m_r[mt * 2 + 1] - mn1);

            float rs0 = 0.f, rs1 = 0.f;
#pragma unroll
            for (int nt = 0; nt < 8; ++nt) {
                float p0 = ex2f(sacc[mt][nt][0] - mn0);
                float p1 = ex2f(sacc[mt][nt][1] - mn0);
                float p2 = ex2f(sacc[mt][nt][2] - mn1);
                float p3 = ex2f(sacc[mt][nt][3] - mn1);
                rs0 += p0 + p1;
                rs1 += p2 + p3;
                int ks = nt >> 1;
                int lo = (nt & 1) << 1;      // 0 or 2
                pa[ks][mt][lo + 0] = packh2(p0, p1);
                pa[ks][mt][lo + 1] = packh2(p2, p3);
            }
            rs0 += __shfl_xor_sync(0xffffffffu, rs0, 1);
            rs0 += __shfl_xor_sync(0xffffffffu, rs0, 2);
            rs1 += __shfl_xor_sync(0xffffffffu, rs1, 1);
            rs1 += __shfl_xor_sync(0xffffffffu, rs1, 2);

            l_r[mt * 2 + 0] = l_r[mt * 2 + 0] * corr0 + rs0;
            l_r[mt * 2 + 1] = l_r[mt * 2 + 1] * corr1 + rs1;
            m_r[mt * 2 + 0] = mn0;
            m_r[mt * 2 + 1] = mn1;

#pragma unroll
            for (int nt = 0; nt < 8; ++nt) {
                oacc[mt][nt][0] *= corr0; oacc[mt][nt][1] *= corr0;
                oacc[mt][nt][2] *= corr1; oacc[mt][nt][3] *= corr1;
            }
        }

        // ---- O += P @ V (V transposed tile: rows d, cols key) ----
#pragma unroll
        for (int ks = 0; ks < 4; ++ks) {
#pragma unroll
            for (int nt = 0; nt < 8; ++nt) {
                int base = (nt * 8 + g) * FSTR_W + 8 * ks + tg;
                uint32_t b0 = Vb[base];
                uint32_t b1 = Vb[base + 4];
                mma_f16(oacc[0][nt], pa[ks][0], b0, b1);
                mma_f16(oacc[1][nt], pa[ks][1], b0, b1);
            }
        }
        __syncthreads();   // all warps done with this K/V buffer
    }

    // ---- epilogue: normalize, round to tf32 bits, write concat-head -------
    float* Og = g_att + (size_t)(b * T_ + t0) * C_ + h * D_;
#pragma unroll
    for (int mt = 0; mt < 2; ++mt) {
        float inv0 = 1.f / l_r[mt * 2 + 0];
        float inv1 = 1.f / l_r[mt * 2 + 1];
        int row = m0 + mt * 16 + g;
#pragma unroll
        for (int nt = 0; nt < 8; ++nt) {
            int col = (nt << 3) + (tg << 1);
            float2 o0, o1;
            o0.x = __uint_as_float(f2tf(oacc[mt][nt][0] * inv0));
            o0.y = __uint_as_float(f2tf(oacc[mt][nt][1] * inv0));
            o1.x = __uint_as_float(f2tf(oacc[mt][nt][2] * inv1));
            o1.y = __uint_as_float(f2tf(oacc[mt][nt][3] * inv1));
            *(float2*)(Og + (size_t)row * C_ + col)       = o0;
            *(float2*)(Og + (size_t)(row + 8) * C_ + col) = o1;
        }
    }
}

// ---------------- launch ---------------------------------------------------
extern "C" void kernel_launch(void* const* d_in, const int* in_sizes, int n_in,
                              void* d_out, int out_size)
{
    const float* x  = (const float*)d_in[0];
    const float* wq = (const float*)d_in[1];
    const float* bq = (const float*)d_in[2];
    const float* wk = (const float*)d_in[3];
    const float* bk = (const float*)d_in[4];
    const float* wv = (const float*)d_in[5];
    const float* bv = (const float*)d_in[6];
    const float* wo = (const float*)d_in[7];
    const float* bo = (const float*)d_in[8];
    float* out = (float*)d_out;

    cudaFuncSetAttribute(qkv_kernel,
                         cudaFuncAttributeMaxDynamicSharedMemorySize, G_SMEM_BYTES);
    cudaFuncSetAttribute(out_kernel,
                         cudaFuncAttributeMaxDynamicSharedMemorySize, G_SMEM_BYTES);

    convx_kernel<<<BT_ * C_ / 4 / 256, 256>>>(x);
    convw_kernel<<<dim3(C_ * C_ / 4 / 256, 4), 256>>>(wq, wk, wv, wo);
    qkv_kernel<<<dim3(C_ / 128, BT_ / 128, 3), 256, G_SMEM_BYTES>>>(bq, bk, bv);
    flash_kernel<<<dim3(T_ / 256, B_ * H_), 256, FSMEM_BYTES>>>();
    out_kernel<<<dim3(C_ / 128, BT_ / 128), 256, G_SMEM_BYTES>>>(bo, out);
}

// round 9
// speedup vs baseline: 2.4654x; 1.4307x over previous
#include <cuda_runtime.h>
#include <cuda_fp16.h>
#include <cstdint>
#include <math.h>

#define B_  2
#define T_  2048
#define C_  1024
#define H_  16
#define D_  64
#define BT_ 4096

// ---------------- scratch (allocation-free contract: __device__ globals) ----
__device__ __half g_qh[BT_ * C_];          // Q fp16 (rope+scale*log2e applied)
__device__ __half g_kh[BT_ * C_];          // K fp16 (rope applied)
__device__ __half g_vt[B_ * H_ * D_ * T_]; // V fp16 transposed [b][h][d][t]
__device__ __half g_atth[BT_ * C_];        // attention output, fp16
__device__ __half g_xh[BT_ * C_];          // x pre-rounded to fp16
__device__ __half g_wh[4 * C_ * C_];       // wq,wk,wv,wo pre-rounded to fp16

// ---------------- helpers ---------------------------------------------------
__device__ __forceinline__ uint32_t smem_u32(const void* p) {
    uint32_t a;
    asm("{ .reg .u64 t; cvta.to.shared.u64 t, %1; cvt.u32.u64 %0, t; }"
        : "=r"(a) : "l"(p));
    return a;
}

__device__ __forceinline__ float ex2f(float x) {
    float r;
    asm("ex2.approx.ftz.f32 %0, %1;" : "=f"(r) : "f"(x));
    return r;
}

__device__ __forceinline__ uint32_t packh2(float lo, float hi) {
    __half2 t = __floats2half2_rn(lo, hi);
    return *(uint32_t*)&t;
}

__device__ __forceinline__ void mma_f16(float c[4], const uint32_t a[4],
                                        uint32_t b0, uint32_t b1) {
    asm volatile(
        "mma.sync.aligned.m16n8k16.row.col.f32.f16.f16.f32 "
        "{%0,%1,%2,%3}, {%4,%5,%6,%7}, {%8,%9}, {%0,%1,%2,%3};\n"
        : "+f"(c[0]), "+f"(c[1]), "+f"(c[2]), "+f"(c[3])
        : "r"(a[0]), "r"(a[1]), "r"(a[2]), "r"(a[3]),
          "r"(b0), "r"(b1));
}

__device__ __forceinline__ void cpa16(uint32_t saddr, const void* g) {
    asm volatile("cp.async.cg.shared.global [%0], [%1], 16;"
                 :: "r"(saddr), "l"(g) : "memory");
}
#define CP_COMMIT() asm volatile("cp.async.commit_group;" ::: "memory")
#define CP_WAIT1()  asm volatile("cp.async.wait_group 1;" ::: "memory")
#define CP_WAIT0()  asm volatile("cp.async.wait_group 0;" ::: "memory")

__device__ __forceinline__ void rope2(float& e, float& o, float t,
                                      float f0, float f1, float scale) {
    float s0, c0, s1, c1;
    sincosf(t * f0, &s0, &c0);
    sincosf(t * f1, &s1, &c1);
    float en = (e * c0 - o * s0) * scale;
    float on = (o * c1 + e * s1) * scale;
    e = en; o = on;
}

#define ROPE_LG 0.41524103786091404f   // log2(10000)*2/64
#define QSCALE  0.18033688011112042f   // 0.125 * log2(e)

// ---------------- fp16 pre-convert kernels ---------------------------------
__global__ __launch_bounds__(256) void convx_kernel(const float* __restrict__ s)
{
    int i = blockIdx.x * 256 + threadIdx.x;        // over BT*C/8
    float4 v0 = ((const float4*)s)[2 * i];
    float4 v1 = ((const float4*)s)[2 * i + 1];
    uint4 u;
    u.x = packh2(v0.x, v0.y); u.y = packh2(v0.z, v0.w);
    u.z = packh2(v1.x, v1.y); u.w = packh2(v1.z, v1.w);
    ((uint4*)g_xh)[i] = u;
}

__global__ __launch_bounds__(256) void convw_kernel(
    const float* __restrict__ wq, const float* __restrict__ wk,
    const float* __restrict__ wv, const float* __restrict__ wo)
{
    const float* src;
    int z = blockIdx.y;
    if (z == 0)      src = wq;
    else if (z == 1) src = wk;
    else if (z == 2) src = wv;
    else             src = wo;
    int i = blockIdx.x * 256 + threadIdx.x;        // over C*C/8
    float4 v0 = ((const float4*)src)[2 * i];
    float4 v1 = ((const float4*)src)[2 * i + 1];
    uint4 u;
    u.x = packh2(v0.x, v0.y); u.y = packh2(v0.z, v0.w);
    u.z = packh2(v1.x, v1.y); u.w = packh2(v1.z, v1.w);
    ((uint4*)(g_wh + (size_t)z * C_ * C_))[i] = u;
}

// ---------------- fp16 GEMM: C[M,N] = A[M,K] @ W[N,K]^T + bias --------------
// A, W fp16. block 128x128, BK=64 halfs (128B/row), 256 threads = 8 warps
// (warp tile 32m x 64n), m16n8k16. cp.async double buffer, stride 36 words
// (72 halfs) per row: fragment reads hit banks (4g+tg) — conflict-free.
// mode: 0 = fp32 out + bias, 1 = Q->fp16 rope, 2 = K->fp16 rope, 3 = V transp.
#define GH_STR 36
#define GH_STAGE_W (2 * 128 * GH_STR)          // A+B words per stage = 9216
#define GH_SMEM_BYTES (2 * GH_STAGE_W * 4)     // 73728

__device__ __forceinline__ void gemm_f16_body(
    const __half* __restrict__ A, const __half* __restrict__ W,
    const float* __restrict__ bias, float* __restrict__ Cm,
    int bx, int by, int mode)
{
    extern __shared__ uint32_t gsm[];

    const int K = C_, N = C_;
    const int tid  = threadIdx.x;
    const int warp = tid >> 5;
    const int lane = tid & 31;
    const int g    = lane >> 2;
    const int tg   = lane & 3;
    const int m0   = (warp & 3) * 32;
    const int n0   = (warp >> 2) * 64;
    const int bm   = by * 128;
    const int bn   = bx * 128;

    const uint32_t smem_base = smem_u32(gsm);
    const __half* Ap = A + (size_t)bm * K;
    const __half* Wp = W + (size_t)bn * K;

    float acc[2][8][4];
#pragma unroll
    for (int mt = 0; mt < 2; ++mt)
#pragma unroll
        for (int nt = 0; nt < 8; ++nt)
#pragma unroll
            for (int i = 0; i < 4; ++i) acc[mt][nt][i] = 0.f;

    auto issue = [&](int kb) {
        const int buf = kb & 1;
        uint32_t sa = smem_base + (buf * GH_STAGE_W) * 4;
        uint32_t sb = sa + 128 * GH_STR * 4;
        const __half* Ak = Ap + kb * 64;
        const __half* Wk = Wp + kb * 64;
#pragma unroll
        for (int i = 0; i < 4; ++i) {
            int id = tid + (i << 8);
            int r  = id >> 3;
            int c  = id & 7;                       // 16B chunk = 8 halfs
            cpa16(sa + (r * GH_STR + c * 4) * 4, Ak + (size_t)r * K + c * 8);
            cpa16(sb + (r * GH_STR + c * 4) * 4, Wk + (size_t)r * K + c * 8);
        }
    };

    issue(0);
    CP_COMMIT();

    const int NKB = K / 64;   // 16
    for (int kb = 0; kb < NKB; ++kb) {
        if (kb + 1 < NKB) {
            issue(kb + 1);
            CP_COMMIT();
            CP_WAIT1();
        } else {
            CP_WAIT0();
        }
        __syncthreads();

        const uint32_t* As = gsm + (kb & 1) * GH_STAGE_W;
        const uint32_t* Bs = As + 128 * GH_STR;

#pragma unroll
        for (int ks = 0; ks < 4; ++ks) {
            const int k0 = ks * 8;                 // word offset (16 halfs)
            uint32_t a[2][4], b[8][2];
#pragma unroll
            for (int mt = 0; mt < 2; ++mt) {
                int row = m0 + mt * 16 + g;
                a[mt][0] = As[row * GH_STR + k0 + tg];
                a[mt][1] = As[(row + 8) * GH_STR + k0 + tg];
                a[mt][2] = As[row * GH_STR + k0 + tg + 4];
                a[mt][3] = As[(row + 8) * GH_STR + k0 + tg + 4];
            }
#pragma unroll
            for (int nt = 0; nt < 8; ++nt) {
                int rn = n0 + nt * 8 + g;
                b[nt][0] = Bs[rn * GH_STR + k0 + tg];
                b[nt][1] = Bs[rn * GH_STR + k0 + tg + 4];
            }
#pragma unroll
            for (int mt = 0; mt < 2; ++mt)
#pragma unroll
                for (int nt = 0; nt < 8; ++nt)
                    mma_f16(acc[mt][nt], a[mt], b[nt][0], b[nt][1]);
        }
        __syncthreads();
    }

    // ---- epilogue ----------------------------------------------------------
    const bool do_rope = (mode == 1 || mode == 2);
    const float rscale = (mode == 1) ? QSCALE : 1.f;
#pragma unroll
    for (int nt = 0; nt < 8; ++nt) {
        int col = bn + n0 + nt * 8 + (tg << 1);
        float2 bv = *(const float2*)(bias + col);
        float f0 = 0.f, f1 = 0.f;
        if (do_rope) {
            int d0 = col & (D_ - 1);
            f0 = exp2f(-ROPE_LG * (float)(d0 & 31));
            f1 = exp2f(-ROPE_LG * (float)((d0 + 1) & 31));
        }
#pragma unroll
        for (int mt = 0; mt < 2; ++mt) {
            int row = bm + m0 + mt * 16 + g;
            float e0 = acc[mt][nt][0] + bv.x, o0 = acc[mt][nt][1] + bv.y;
            float e1 = acc[mt][nt][2] + bv.x, o1 = acc[mt][nt][3] + bv.y;
            if (do_rope) {
                rope2(e0, o0, (float)(row & (T_ - 1)), f0, f1, rscale);
                rope2(e1, o1, (float)((row + 8) & (T_ - 1)), f0, f1, rscale);
            }
            if (mode == 1 || mode == 2) {
                __half* dst = (mode == 1 ? g_qh : g_kh);
                *(__half2*)(dst + (size_t)row * N + col) =
                    __floats2half2_rn(e0, o0);
                *(__half2*)(dst + (size_t)(row + 8) * N + col) =
                    __floats2half2_rn(e1, o1);
            } else if (mode == 3) {
                int h = col >> 6, d = col & 63;
                int b = row >> 11;
                int t = row & (T_ - 1);
                __half* base = g_vt + ((size_t)(b * H_ + h) * D_) * T_;
                base[(size_t)d * T_ + t]            = __float2half_rn(e0);
                base[(size_t)(d + 1) * T_ + t]      = __float2half_rn(o0);
                base[(size_t)d * T_ + t + 8]        = __float2half_rn(e1);
                base[(size_t)(d + 1) * T_ + t + 8]  = __float2half_rn(o1);
            } else {
                *(float2*)(Cm + (size_t)row * N + col)       = make_float2(e0, o0);
                *(float2*)(Cm + (size_t)(row + 8) * N + col) = make_float2(e1, o1);
            }
        }
    }
}

__global__ __launch_bounds__(256, 2) void qkv_kernel(
    const float* __restrict__ bq, const float* __restrict__ bk,
    const float* __restrict__ bv)
{
    const float* bb; int mode;
    int z = blockIdx.z;
    if (z == 0)      { bb = bq; mode = 1; }
    else if (z == 1) { bb = bk; mode = 2; }
    else             { bb = bv; mode = 3; }
    gemm_f16_body(g_xh, g_wh + (size_t)z * C_ * C_, bb, nullptr,
                  blockIdx.x, blockIdx.y, mode);
}

__global__ __launch_bounds__(256, 2) void out_kernel(
    const float* __restrict__ bo, float* __restrict__ out)
{
    gemm_f16_body(g_atth, g_wh + (size_t)3 * C_ * C_, bo, out,
                  blockIdx.x, blockIdx.y, 0);
}

// ---------------- flash attention (fp16 m16n8k16, Br=256, Bc=64) -----------
// unchanged from round 8 except the epilogue stores fp16 into g_atth.
#define FSTR_W 36                           // 72 halfs per row
#define F_STAGE_W (2 * 64 * FSTR_W)         // K+V words per stage = 4608
#define FSMEM_BYTES (2 * F_STAGE_W * 4)     // 36864

__global__ __launch_bounds__(256) void flash_kernel()
{
    extern __shared__ uint32_t sm[];

    const int bh = blockIdx.y;
    const int b  = bh >> 4;
    const int h  = bh & 15;
    const int t0 = blockIdx.x << 8;
    const int tid  = threadIdx.x;
    const int warp = tid >> 5;
    const int lane = tid & 31;
    const int g    = lane >> 2;
    const int tg   = lane & 3;
    const int m0   = warp << 5;

    const uint32_t smem_base = smem_u32(sm);
    const __half* Kg0 = g_kh + (size_t)(b * T_) * C_ + h * D_;
    const __half* Vt0 = g_vt + (size_t)(b * H_ + h) * D_ * T_;

    auto issue_kv = [&](int kt) {
        const int buf = kt & 1;
        const uint32_t kb = smem_base + (buf * F_STAGE_W) * 4;
        const uint32_t vb = kb + 64 * FSTR_W * 4;
#pragma unroll
        for (int i = 0; i < 2; ++i) {
            int id = tid + (i << 8);
            int r  = id >> 3;
            int c  = id & 7;
            cpa16(kb + (r * FSTR_W + c * 4) * 4,
                  Kg0 + (size_t)(kt * 64 + r) * C_ + c * 8);
            cpa16(vb + (r * FSTR_W + c * 4) * 4,
                  Vt0 + (size_t)r * T_ + kt * 64 + c * 8);
        }
    };

    issue_kv(0);
    CP_COMMIT();

    // ---- Q fragments, kt-invariant, direct from gmem into registers ------
    uint32_t qa[4][2][4];
    const __half* Qg = g_qh + (size_t)(b * T_ + t0 + m0) * C_ + h * D_;
#pragma unroll
    for (int ks = 0; ks < 4; ++ks)
#pragma unroll
        for (int mt = 0; mt < 2; ++mt) {
            const __half* p0 = Qg + (size_t)(mt * 16 + g) * C_ + 16 * ks + 2 * tg;
            const __half* p1 = p0 + 8 * C_;
            qa[ks][mt][0] = *(const uint32_t*)p0;
            qa[ks][mt][1] = *(const uint32_t*)p1;
            qa[ks][mt][2] = *(const uint32_t*)(p0 + 8);
            qa[ks][mt][3] = *(const uint32_t*)(p1 + 8);
        }

    float oacc[2][8][4];
    float m_r[4], l_r[4];
#pragma unroll
    for (int mt = 0; mt < 2; ++mt)
#pragma unroll
        for (int nt = 0; nt < 8; ++nt)
#pragma unroll
            for (int i = 0; i < 4; ++i) oacc[mt][nt][i] = 0.f;
#pragma unroll
    for (int i = 0; i < 4; ++i) { m_r[i] = -1e30f; l_r[i] = 0.f; }

    const int NKT = T_ / 64;   // 32
    for (int kt = 0; kt < NKT; ++kt) {
        if (kt + 1 < NKT) {
            issue_kv(kt + 1);
            CP_COMMIT();
            CP_WAIT1();
        } else {
            CP_WAIT0();
        }
        __syncthreads();

        const uint32_t* Kb = sm + (kt & 1) * F_STAGE_W;
        const uint32_t* Vb = Kb + 64 * FSTR_W;

        // ---- S = Q @ K^T (log2-scaled) ----
        float sacc[2][8][4];
#pragma unroll
        for (int mt = 0; mt < 2; ++mt)
#pragma unroll
            for (int nt = 0; nt < 8; ++nt)
#pragma unroll
                for (int i = 0; i < 4; ++i) sacc[mt][nt][i] = 0.f;

#pragma unroll
        for (int ks = 0; ks < 4; ++ks) {
#pragma unroll
            for (int nt = 0; nt < 8; ++nt) {
                int base = (nt * 8 + g) * FSTR_W + 8 * ks + tg;
                uint32_t b0 = Kb[base];
                uint32_t b1 = Kb[base + 4];
                mma_f16(sacc[0][nt], qa[ks][0], b0, b1);
                mma_f16(sacc[1][nt], qa[ks][1], b0, b1);
            }
        }

        // ---- online softmax (log2 domain) + pack P to fp16 A-fragments ----
        uint32_t pa[4][2][4];
#pragma unroll
        for (int mt = 0; mt < 2; ++mt) {
            float mx0 = -1e30f, mx1 = -1e30f;
#pragma unroll
            for (int nt = 0; nt < 8; ++nt) {
                mx0 = fmaxf(mx0, fmaxf(sacc[mt][nt][0], sacc[mt][nt][1]));
                mx1 = fmaxf(mx1, fmaxf(sacc[mt][nt][2], sacc[mt][nt][3]));
            }
            mx0 = fmaxf(mx0, __shfl_xor_sync(0xffffffffu, mx0, 1));
            mx0 = fmaxf(mx0, __shfl_xor_sync(0xffffffffu, mx0, 2));
            mx1 = fmaxf(mx1, __shfl_xor_sync(0xffffffffu, mx1, 1));
            mx1 = fmaxf(mx1, __shfl_xor_sync(0xffffffffu, mx1, 2));

            float mn0 = fmaxf(m_r[mt * 2 + 0], mx0);
            float mn1 = fmaxf(m_r[mt * 2 + 1], mx1);
            float corr0 = ex2f(m_r[mt * 2 + 0] - mn0);
            float corr1 = ex2f(m_r[mt * 2 + 1] - mn1);

            float rs0 = 0.f, rs1 = 0.f;
#pragma unroll
            for (int nt = 0; nt < 8; ++nt) {
                float p0 = ex2f(sacc[mt][nt][0] - mn0);
                float p1 = ex2f(sacc[mt][nt][1] - mn0);
                float p2 = ex2f(sacc[mt][nt][2] - mn1);
                float p3 = ex2f(sacc[mt][nt][3] - mn1);
                rs0 += p0 + p1;
                rs1 += p2 + p3;
                int ks = nt >> 1;
                int lo = (nt & 1) << 1;
                pa[ks][mt][lo + 0] = packh2(p0, p1);
                pa[ks][mt][lo + 1] = packh2(p2, p3);
            }
            rs0 += __shfl_xor_sync(0xffffffffu, rs0, 1);
            rs0 += __shfl_xor_sync(0xffffffffu, rs0, 2);
            rs1 += __shfl_xor_sync(0xffffffffu, rs1, 1);
            rs1 += __shfl_xor_sync(0xffffffffu, rs1, 2);

            l_r[mt * 2 + 0] = l_r[mt * 2 + 0] * corr0 + rs0;
            l_r[mt * 2 + 1] = l_r[mt * 2 + 1] * corr1 + rs1;
            m_r[mt * 2 + 0] = mn0;
            m_r[mt * 2 + 1] = mn1;

#pragma unroll
            for (int nt = 0; nt < 8; ++nt) {
                oacc[mt][nt][0] *= corr0; oacc[mt][nt][1] *= corr0;
                oacc[mt][nt][2] *= corr1; oacc[mt][nt][3] *= corr1;
            }
        }

        // ---- O += P @ V (V transposed tile: rows d, cols key) ----
#pragma unroll
        for (int ks = 0; ks < 4; ++ks) {
#pragma unroll
            for (int nt = 0; nt < 8; ++nt) {
                int base = (nt * 8 + g) * FSTR_W + 8 * ks + tg;
                uint32_t b0 = Vb[base];
                uint32_t b1 = Vb[base + 4];
                mma_f16(oacc[0][nt], pa[ks][0], b0, b1);
                mma_f16(oacc[1][nt], pa[ks][1], b0, b1);
            }
        }
        __syncthreads();
    }

    // ---- epilogue: normalize, write fp16 concat-head ----------------------
    __half* Og = g_atth + (size_t)(b * T_ + t0) * C_ + h * D_;
#pragma unroll
    for (int mt = 0; mt < 2; ++mt) {
        float inv0 = 1.f / l_r[mt * 2 + 0];
        float inv1 = 1.f / l_r[mt * 2 + 1];
        int row = m0 + mt * 16 + g;
#pragma unroll
        for (int nt = 0; nt < 8; ++nt) {
            int col = (nt << 3) + (tg << 1);
            *(__half2*)(Og + (size_t)row * C_ + col) =
                __floats2half2_rn(oacc[mt][nt][0] * inv0,
                                  oacc[mt][nt][1] * inv0);
            *(__half2*)(Og + (size_t)(row + 8) * C_ + col) =
                __floats2half2_rn(oacc[mt][nt][2] * inv1,
                                  oacc[mt][nt][3] * inv1);
        }
    }
}

// ---------------- launch ---------------------------------------------------
extern "C" void kernel_launch(void* const* d_in, const int* in_sizes, int n_in,
                              void* d_out, int out_size)
{
    const float* x  = (const float*)d_in[0];
    const float* wq = (const float*)d_in[1];
    const float* bq = (const float*)d_in[2];
    const float* wk = (const float*)d_in[3];
    const float* bk = (const float*)d_in[4];
    const float* wv = (const float*)d_in[5];
    const float* bv = (const float*)d_in[6];
    const float* wo = (const float*)d_in[7];
    const float* bo = (const float*)d_in[8];
    float* out = (float*)d_out;

    cudaFuncSetAttribute(qkv_kernel,
                         cudaFuncAttributeMaxDynamicSharedMemorySize, GH_SMEM_BYTES);
    cudaFuncSetAttribute(out_kernel,
                         cudaFuncAttributeMaxDynamicSharedMemorySize, GH_SMEM_BYTES);

    convx_kernel<<<BT_ * C_ / 8 / 256, 256>>>(x);
    convw_kernel<<<dim3(C_ * C_ / 8 / 256, 4), 256>>>(wq, wk, wv, wo);
    qkv_kernel<<<dim3(C_ / 128, BT_ / 128, 3), 256, GH_SMEM_BYTES>>>(bq, bk, bv);
    flash_kernel<<<dim3(T_ / 256, B_ * H_), 256, FSMEM_BYTES>>>();
    out_kernel<<<dim3(C_ / 128, BT_ / 128), 256, GH_SMEM_BYTES>>>(bo, out);
}

// round 11
// speedup vs baseline: 2.5908x; 1.0509x over previous
#include <cuda_runtime.h>
#include <cuda_fp16.h>
#include <cstdint>
#include <math.h>

#define B_  2
#define T_  2048
#define C_  1024
#define H_  16
#define D_  64
#define BT_ 4096

// ---------------- scratch (allocation-free contract: __device__ globals) ----
__device__ __half g_qh[BT_ * C_];          // Q fp16 (rope+scale*log2e applied)
__device__ __half g_kh[BT_ * C_];          // K fp16 (rope applied)
__device__ __half g_vt[B_ * H_ * D_ * T_]; // V fp16 transposed [b][h][d][t]
__device__ __half g_atth[BT_ * C_];        // attention output, fp16
__device__ __half g_xh[BT_ * C_];          // x pre-rounded to fp16
__device__ __half g_wh[4 * C_ * C_];       // wq,wk,wv,wo pre-rounded to fp16

// ---------------- helpers ---------------------------------------------------
__device__ __forceinline__ uint32_t smem_u32(const void* p) {
    uint32_t a;
    asm("{ .reg .u64 t; cvta.to.shared.u64 t, %1; cvt.u32.u64 %0, t; }"
        : "=r"(a) : "l"(p));
    return a;
}

__device__ __forceinline__ float ex2f(float x) {
    float r;
    asm("ex2.approx.ftz.f32 %0, %1;" : "=f"(r) : "f"(x));
    return r;
}

__device__ __forceinline__ uint32_t packh2(float lo, float hi) {
    __half2 t = __floats2half2_rn(lo, hi);
    return *(uint32_t*)&t;
}

__device__ __forceinline__ void mma_f16r(float c[4], uint32_t a0, uint32_t a1,
                                         uint32_t a2, uint32_t a3,
                                         uint32_t b0, uint32_t b1) {
    asm volatile(
        "mma.sync.aligned.m16n8k16.row.col.f32.f16.f16.f32 "
        "{%0,%1,%2,%3}, {%4,%5,%6,%7}, {%8,%9}, {%0,%1,%2,%3};\n"
        : "+f"(c[0]), "+f"(c[1]), "+f"(c[2]), "+f"(c[3])
        : "r"(a0), "r"(a1), "r"(a2), "r"(a3), "r"(b0), "r"(b1));
}

#define LDSM_X4(r0, r1, r2, r3, addr) \
    asm volatile("ldmatrix.sync.aligned.m8n8.x4.shared.b16 {%0,%1,%2,%3}, [%4];" \
                 : "=r"(r0), "=r"(r1), "=r"(r2), "=r"(r3) : "r"(addr))

__device__ __forceinline__ void cpa16(uint32_t saddr, const void* g) {
    asm volatile("cp.async.cg.shared.global [%0], [%1], 16;"
                 :: "r"(saddr), "l"(g) : "memory");
}
#define CP_COMMIT() asm volatile("cp.async.commit_group;" ::: "memory")
#define CP_WAIT1()  asm volatile("cp.async.wait_group 1;" ::: "memory")
#define CP_WAIT0()  asm volatile("cp.async.wait_group 0;" ::: "memory")

__device__ __forceinline__ void rope2(float& e, float& o, float t,
                                      float f0, float f1, float scale) {
    float s0, c0, s1, c1;
    sincosf(t * f0, &s0, &c0);
    sincosf(t * f1, &s1, &c1);
    float en = (e * c0 - o * s0) * scale;
    float on = (o * c1 + e * s1) * scale;
    e = en; o = on;
}

#define ROPE_LG 0.41524103786091404f   // log2(10000)*2/64
#define QSCALE  0.18033688011112042f   // 0.125 * log2(e)

// ---------------- fp16 pre-convert kernels ---------------------------------
__global__ __launch_bounds__(256) void convx_kernel(const float* __restrict__ s)
{
    int i = blockIdx.x * 256 + threadIdx.x;
    float4 v0 = ((const float4*)s)[2 * i];
    float4 v1 = ((const float4*)s)[2 * i + 1];
    uint4 u;
    u.x = packh2(v0.x, v0.y); u.y = packh2(v0.z, v0.w);
    u.z = packh2(v1.x, v1.y); u.w = packh2(v1.z, v1.w);
    ((uint4*)g_xh)[i] = u;
}

__global__ __launch_bounds__(256) void convw_kernel(
    const float* __restrict__ wq, const float* __restrict__ wk,
    const float* __restrict__ wv, const float* __restrict__ wo)
{
    const float* src;
    int z = blockIdx.y;
    if (z == 0)      src = wq;
    else if (z == 1) src = wk;
    else if (z == 2) src = wv;
    else             src = wo;
    int i = blockIdx.x * 256 + threadIdx.x;
    float4 v0 = ((const float4*)src)[2 * i];
    float4 v1 = ((const float4*)src)[2 * i + 1];
    uint4 u;
    u.x = packh2(v0.x, v0.y); u.y = packh2(v0.z, v0.w);
    u.z = packh2(v1.x, v1.y); u.w = packh2(v1.z, v1.w);
    ((uint4*)(g_wh + (size_t)z * C_ * C_))[i] = u;
}

// ---------------- fp16 GEMM: C[M,N] = A[M,K] @ W[N,K]^T + bias --------------
// block 128x128, BK=64 halfs, 256 threads = 8 warps (warp tile 32m x 64n),
// m16n8k16, fragments via ldmatrix.x4. Stride 36 words/row: ldmatrix phases
// hit banks 4r..4r+3 over 8 rows -> conflict-free.
#define GH_STR 36
#define GH_STAGE_W (2 * 128 * GH_STR)
#define GH_SMEM_BYTES (2 * GH_STAGE_W * 4)

__device__ __forceinline__ void gemm_f16_body(
    const __half* __restrict__ A, const __half* __restrict__ W,
    const float* __restrict__ bias, float* __restrict__ Cm,
    int bx, int by, int mode)
{
    extern __shared__ uint32_t gsm[];

    const int K = C_, N = C_;
    const int tid  = threadIdx.x;
    const int warp = tid >> 5;
    const int lane = tid & 31;
    const int g    = lane >> 2;
    const int tg   = lane & 3;
    const int m0   = (warp & 3) * 32;
    const int n0   = (warp >> 2) * 64;
    const int bm   = by * 128;
    const int bn   = bx * 128;

    const uint32_t smem_base = smem_u32(gsm);
    const __half* Ap = A + (size_t)bm * K;
    const __half* Wp = W + (size_t)bn * K;

    // ldmatrix lane address components
    const int arow = (lane & 7) + ((lane >> 3) & 1) * 8;   // A: row within 16
    const int akof = (lane >> 4) * 4;                      // A: k word offset
    const int brow = lane & 7;                             // B: row within 8
    const int bkof = ((lane >> 3) & 1) * 4;                // B: k word offset
    const int bns  = (lane >> 4) * 8;                      // B: nt-pair select

    float acc[2][8][4];
#pragma unroll
    for (int mt = 0; mt < 2; ++mt)
#pragma unroll
        for (int nt = 0; nt < 8; ++nt)
#pragma unroll
            for (int i = 0; i < 4; ++i) acc[mt][nt][i] = 0.f;

    auto issue = [&](int kb) {
        const int buf = kb & 1;
        uint32_t sa = smem_base + (buf * GH_STAGE_W) * 4;
        uint32_t sb = sa + 128 * GH_STR * 4;
        const __half* Ak = Ap + kb * 64;
        const __half* Wk = Wp + kb * 64;
#pragma unroll
        for (int i = 0; i < 4; ++i) {
            int id = tid + (i << 8);
            int r  = id >> 3;
            int c  = id & 7;
            cpa16(sa + (r * GH_STR + c * 4) * 4, Ak + (size_t)r * K + c * 8);
            cpa16(sb + (r * GH_STR + c * 4) * 4, Wk + (size_t)r * K + c * 8);
        }
    };

    issue(0);
    CP_COMMIT();

    const int NKB = K / 64;   // 16
    for (int kb = 0; kb < NKB; ++kb) {
        if (kb + 1 < NKB) {
            issue(kb + 1);
            CP_COMMIT();
            CP_WAIT1();
        } else {
            CP_WAIT0();
        }
        __syncthreads();

        const uint32_t As = smem_base + ((kb & 1) * GH_STAGE_W) * 4;
        const uint32_t Bs = As + 128 * GH_STR * 4;
        const uint32_t aAddr0 = As + ((m0 + arow) * GH_STR + akof) * 4;
        const uint32_t aAddr1 = As + ((m0 + 16 + arow) * GH_STR + akof) * 4;
        const uint32_t bAddr  = Bs + ((n0 + bns + brow) * GH_STR + bkof) * 4;

#pragma unroll
        for (int ks = 0; ks < 4; ++ks) {
            const int ko = ks * 8 * 4;          // byte offset for this k-step
            uint32_t a[2][4], b[8][2];
            LDSM_X4(a[0][0], a[0][1], a[0][2], a[0][3], aAddr0 + ko);
            LDSM_X4(a[1][0], a[1][1], a[1][2], a[1][3], aAddr1 + ko);
#pragma unroll
            for (int ntp = 0; ntp < 4; ++ntp) {
                LDSM_X4(b[2 * ntp][0], b[2 * ntp][1],
                        b[2 * ntp + 1][0], b[2 * ntp + 1][1],
                        bAddr + (ntp * 16 * GH_STR) * 4 + ko);
            }
#pragma unroll
            for (int mt = 0; mt < 2; ++mt)
#pragma unroll
                for (int nt = 0; nt < 8; ++nt)
                    mma_f16r(acc[mt][nt], a[mt][0], a[mt][1], a[mt][2],
                             a[mt][3], b[nt][0], b[nt][1]);
        }
        __syncthreads();
    }

    // ---- epilogue ----------------------------------------------------------
    const bool do_rope = (mode == 1 || mode == 2);
    const float rscale = (mode == 1) ? QSCALE : 1.f;
#pragma unroll
    for (int nt = 0; nt < 8; ++nt) {
        int col = bn + n0 + nt * 8 + (tg << 1);
        float2 bv = *(const float2*)(bias + col);
        float f0 = 0.f, f1 = 0.f;
        if (do_rope) {
            int d0 = col & (D_ - 1);
            f0 = exp2f(-ROPE_LG * (float)(d0 & 31));
            f1 = exp2f(-ROPE_LG * (float)((d0 + 1) & 31));
        }
#pragma unroll
        for (int mt = 0; mt < 2; ++mt) {
            int row = bm + m0 + mt * 16 + g;
            float e0 = acc[mt][nt][0] + bv.x, o0 = acc[mt][nt][1] + bv.y;
            float e1 = acc[mt][nt][2] + bv.x, o1 = acc[mt][nt][3] + bv.y;
            if (do_rope) {
                rope2(e0, o0, (float)(row & (T_ - 1)), f0, f1, rscale);
                rope2(e1, o1, (float)((row + 8) & (T_ - 1)), f0, f1, rscale);
            }
            if (mode == 1 || mode == 2) {
                __half* dst = (mode == 1 ? g_qh : g_kh);
                *(__half2*)(dst + (size_t)row * N + col) =
                    __floats2half2_rn(e0, o0);
                *(__half2*)(dst + (size_t)(row + 8) * N + col) =
                    __floats2half2_rn(e1, o1);
            } else if (mode == 3) {
                int h = col >> 6, d = col & 63;
                int b = row >> 11;
                int t = row & (T_ - 1);
                __half* base = g_vt + ((size_t)(b * H_ + h) * D_) * T_;
                base[(size_t)d * T_ + t]            = __float2half_rn(e0);
                base[(size_t)(d + 1) * T_ + t]      = __float2half_rn(o0);
                base[(size_t)d * T_ + t + 8]        = __float2half_rn(e1);
                base[(size_t)(d + 1) * T_ + t + 8]  = __float2half_rn(o1);
            } else {
                *(float2*)(Cm + (size_t)row * N + col)       = make_float2(e0, o0);
                *(float2*)(Cm + (size_t)(row + 8) * N + col) = make_float2(e1, o1);
            }
        }
    }
}

__global__ __launch_bounds__(256, 2) void qkv_kernel(
    const float* __restrict__ bq, const float* __restrict__ bk,
    const float* __restrict__ bv)
{
    const float* bb; int mode;
    int z = blockIdx.z;
    if (z == 0)      { bb = bq; mode = 1; }
    else if (z == 1) { bb = bk; mode = 2; }
    else             { bb = bv; mode = 3; }
    gemm_f16_body(g_xh, g_wh + (size_t)z * C_ * C_, bb, nullptr,
                  blockIdx.x, blockIdx.y, mode);
}

__global__ __launch_bounds__(256, 2) void out_kernel(
    const float* __restrict__ bo, float* __restrict__ out)
{
    gemm_f16_body(g_atth, g_wh + (size_t)3 * C_ * C_, bo, out,
                  blockIdx.x, blockIdx.y, 0);
}

// ---------------- flash attention (fp16 m16n8k16, Br=256, Bc=64) -----------
// K/V fragments via ldmatrix.x4 (4 instr per ks instead of 16 LDS.32).
#define FSTR_W 36
#define F_STAGE_W (2 * 64 * FSTR_W)
#define FSMEM_BYTES (2 * F_STAGE_W * 4)

__global__ __launch_bounds__(256) void flash_kernel()
{
    extern __shared__ uint32_t sm[];

    const int bh = blockIdx.y;
    const int b  = bh >> 4;
    const int h  = bh & 15;
    const int t0 = blockIdx.x << 8;
    const int tid  = threadIdx.x;
    const int warp = tid >> 5;
    const int lane = tid & 31;
    const int g    = lane >> 2;
    const int tg   = lane & 3;
    const int m0   = warp << 5;

    const uint32_t smem_base = smem_u32(sm);
    const __half* Kg0 = g_kh + (size_t)(b * T_) * C_ + h * D_;
    const __half* Vt0 = g_vt + (size_t)(b * H_ + h) * D_ * T_;

    // ldmatrix B lane address components
    const int brow = lane & 7;
    const int bkof = ((lane >> 3) & 1) * 4;
    const int bns  = (lane >> 4) * 8;
    const uint32_t bOffB = ((bns + brow) * FSTR_W + bkof) * 4;

    auto issue_kv = [&](int kt) {
        const int buf = kt & 1;
        const uint32_t kb = smem_base + (buf * F_STAGE_W) * 4;
        const uint32_t vb = kb + 64 * FSTR_W * 4;
#pragma unroll
        for (int i = 0; i < 2; ++i) {
            int id = tid + (i << 8);
            int r  = id >> 3;
            int c  = id & 7;
            cpa16(kb + (r * FSTR_W + c * 4) * 4,
                  Kg0 + (size_t)(kt * 64 + r) * C_ + c * 8);
            cpa16(vb + (r * FSTR_W + c * 4) * 4,
                  Vt0 + (size_t)r * T_ + kt * 64 + c * 8);
        }
    };

    issue_kv(0);
    CP_COMMIT();

    // ---- Q fragments, kt-invariant, direct from gmem into registers ------
    uint32_t qa[4][2][4];
    const __half* Qg = g_qh + (size_t)(b * T_ + t0 + m0) * C_ + h * D_;
#pragma unroll
    for (int ks = 0; ks < 4; ++ks)
#pragma unroll
        for (int mt = 0; mt < 2; ++mt) {
            const __half* p0 = Qg + (size_t)(mt * 16 + g) * C_ + 16 * ks + 2 * tg;
            const __half* p1 = p0 + 8 * C_;
            qa[ks][mt][0] = *(const uint32_t*)p0;
            qa[ks][mt][1] = *(const uint32_t*)p1;
            qa[ks][mt][2] = *(const uint32_t*)(p0 + 8);
            qa[ks][mt][3] = *(const uint32_t*)(p1 + 8);
        }

    float oacc[2][8][4];
    float m_r[4], l_r[4];
#pragma unroll
    for (int mt = 0; mt < 2; ++mt)
#pragma unroll
        for (int nt = 0; nt < 8; ++nt)
#pragma unroll
            for (int i = 0; i < 4; ++i) oacc[mt][nt][i] = 0.f;
#pragma unroll
    for (int i = 0; i < 4; ++i) { m_r[i] = -1e30f; l_r[i] = 0.f; }

    const int NKT = T_ / 64;   // 32
    for (int kt = 0; kt < NKT; ++kt) {
        if (kt + 1 < NKT) {
            issue_kv(kt + 1);
            CP_COMMIT();
            CP_WAIT1();
        } else {
            CP_WAIT0();
        }
        __syncthreads();

        const uint32_t KbA = smem_base + ((kt & 1) * F_STAGE_W) * 4 + bOffB;
        const uint32_t VbA = KbA + 64 * FSTR_W * 4;

        // ---- S = Q @ K^T (log2-scaled) ----
        float sacc[2][8][4];
#pragma unroll
        for (int mt = 0; mt < 2; ++mt)
#pragma unroll
            for (int nt = 0; nt < 8; ++nt)
#pragma unroll
                for (int i = 0; i < 4; ++i) sacc[mt][nt][i] = 0.f;

#pragma unroll
        for (int ks = 0; ks < 4; ++ks) {
            const int ko = ks * 8 * 4;
#pragma unroll
            for (int ntp = 0; ntp < 4; ++ntp) {
                uint32_t b00, b01, b10, b11;
                LDSM_X4(b00, b01, b10, b11,
                        KbA + (ntp * 16 * FSTR_W) * 4 + ko);
                mma_f16r(sacc[0][2 * ntp], qa[ks][0][0], qa[ks][0][1],
                         qa[ks][0][2], qa[ks][0][3], b00, b01);
                mma_f16r(sacc[1][2 * ntp], qa[ks][1][0], qa[ks][1][1],
                         qa[ks][1][2], qa[ks][1][3], b00, b01);
                mma_f16r(sacc[0][2 * ntp + 1], qa[ks][0][0], qa[ks][0][1],
                         qa[ks][0][2], qa[ks][0][3], b10, b11);
                mma_f16r(sacc[1][2 * ntp + 1], qa[ks][1][0], qa[ks][1][1],
                         qa[ks][1][2], qa[ks][1][3], b10, b11);
            }
        }

        // ---- online softmax (log2 domain) + pack P to fp16 A-fragments ----
        uint32_t pa[4][2][4];
#pragma unroll
        for (int mt = 0; mt < 2; ++mt) {
            float mx0 = -1e30f, mx1 = -1e30f;
#pragma unroll
            for (int nt = 0; nt < 8; ++nt) {
                mx0 = fmaxf(mx0, fmaxf(sacc[mt][nt][0], sacc[mt][nt][1]));
                mx1 = fmaxf(mx1, fmaxf(sacc[mt][nt][2], sacc[mt][nt][3]));
            }
            mx0 = fmaxf(mx0, __shfl_xor_sync(0xffffffffu, mx0, 1));
            mx0 = fmaxf(mx0, __shfl_xor_sync(0xffffffffu, mx0, 2));
            mx1 = fmaxf(mx1, __shfl_xor_sync(0xffffffffu, mx1, 1));
            mx1 = fmaxf(mx1, __shfl_xor_sync(0xffffffffu, mx1, 2));

            float mn0 = fmaxf(m_r[mt * 2 + 0], mx0);
            float mn1 = fmaxf(m_r[mt * 2 + 1], mx1);
            float corr0 = ex2f(m_r[mt * 2 + 0] - mn0);
            float corr1 = ex2f(m_r[mt * 2 + 1] - mn1);

            float rs0 = 0.f, rs1 = 0.f;
#pragma unroll
            for (int nt = 0; nt < 8; ++nt) {
                float p0 = ex2f(sacc[mt][nt][0] - mn0);
                float p1 = ex2f(sacc[mt][nt][1] - mn0);
                float p2 = ex2f(sacc[mt][nt][2] - mn1);
                float p3 = ex2f(sacc[mt][nt][3] - mn1);
                rs0 += p0 + p1;
                rs1 += p2 + p3;
                int ks = nt >> 1;
                int lo = (nt & 1) << 1;
                pa[ks][mt][lo + 0] = packh2(p0, p1);
                pa[ks][mt][lo + 1] = packh2(p2, p3);
            }
            rs0 += __shfl_xor_sync(0xffffffffu, rs0, 1);
            rs0 += __shfl_xor_sync(0xffffffffu, rs0, 2);
            rs1 += __shfl_xor_sync(0xffffffffu, rs1, 1);
            rs1 += __shfl_xor_sync(0xffffffffu, rs1, 2);

            l_r[mt * 2 + 0] = l_r[mt * 2 + 0] * corr0 + rs0;
            l_r[mt * 2 + 1] = l_r[mt * 2 + 1] * corr1 + rs1;
            m_r[mt * 2 + 0] = mn0;
            m_r[mt * 2 + 1] = mn1;

#pragma unroll
            for (int nt = 0; nt < 8; ++nt) {
                oacc[mt][nt][0] *= corr0; oacc[mt][nt][1] *= corr0;
                oacc[mt][nt][2] *= corr1; oacc[mt][nt][3] *= corr1;
            }
        }

        // ---- O += P @ V (V transposed tile: rows d, cols key) ----
#pragma unroll
        for (int ks = 0; ks < 4; ++ks) {
            const int ko = ks * 8 * 4;
#pragma unroll
            for (int ntp = 0; ntp < 4; ++ntp) {
                uint32_t b00, b01, b10, b11;
                LDSM_X4(b00, b01, b10, b11,
                        VbA + (ntp * 16 * FSTR_W) * 4 + ko);
                mma_f16r(oacc[0][2 * ntp], pa[ks][0][0], pa[ks][0][1],
                         pa[ks][0][2], pa[ks][0][3], b00, b01);
                mma_f16r(oacc[1][2 * ntp], pa[ks][1][0], pa[ks][1][1],
                         pa[ks][1][2], pa[ks][1][3], b00, b01);
                mma_f16r(oacc[0][2 * ntp + 1], pa[ks][0][0], pa[ks][0][1],
                         pa[ks][0][2], pa[ks][0][3], b10, b11);
                mma_f16r(oacc[1][2 * ntp + 1], pa[ks][1][0], pa[ks][1][1],
                         pa[ks][1][2], pa[ks][1][3], b10, b11);
            }
        }
        __syncthreads();
    }

    // ---- epilogue: normalize, write fp16 concat-head ----------------------
    __half* Og = g_atth + (size_t)(b * T_ + t0) * C_ + h * D_;
#pragma unroll
    for (int mt = 0; mt < 2; ++mt) {
        float inv0 = 1.f / l_r[mt * 2 + 0];
        float inv1 = 1.f / l_r[mt * 2 + 1];
        int row = m0 + mt * 16 + g;
#pragma unroll
        for (int nt = 0; nt < 8; ++nt) {
            int col = (nt << 3) + (tg << 1);
            *(__half2*)(Og + (size_t)row * C_ + col) =
                __floats2half2_rn(oacc[mt][nt][0] * inv0,
                                  oacc[mt][nt][1] * inv0);
            *(__half2*)(Og + (size_t)(row + 8) * C_ + col) =
                __floats2half2_rn(oacc[mt][nt][2] * inv1,
                                  oacc[mt][nt][3] * inv1);
        }
    }
}

// ---------------- launch ---------------------------------------------------
extern "C" void kernel_launch(void* const* d_in, const int* in_sizes, int n_in,
                              void* d_out, int out_size)
{
    const float* x  = (const float*)d_in[0];
    const float* wq = (const float*)d_in[1];
    const float* bq = (const float*)d_in[2];
    const float* wk = (const float*)d_in[3];
    const float* bk = (const float*)d_in[4];
    const float* wv = (const float*)d_in[5];
    const float* bv = (const float*)d_in[6];
    const float* wo = (const float*)d_in[7];
    const float* bo = (const float*)d_in[8];
    float* out = (float*)d_out;

    cudaFuncSetAttribute(qkv_kernel,
                         cudaFuncAttributeMaxDynamicSharedMemorySize, GH_SMEM_BYTES);
    cudaFuncSetAttribute(out_kernel,
                         cudaFuncAttributeMaxDynamicSharedMemorySize, GH_SMEM_BYTES);

    convx_kernel<<<BT_ * C_ / 8 / 256, 256>>>(x);
    convw_kernel<<<dim3(C_ * C_ / 8 / 256, 4), 256>>>(wq, wk, wv, wo);
    qkv_kernel<<<dim3(C_ / 128, BT_ / 128, 3), 256, GH_SMEM_BYTES>>>(bq, bk, bv);
    flash_kernel<<<dim3(T_ / 256, B_ * H_), 256, FSMEM_BYTES>>>();
    out_kernel<<<dim3(C_ / 128, BT_ / 128), 256, GH_SMEM_BYTES>>>(bo, out);
}